// round 1
// baseline (speedup 1.0000x reference)
#include <cuda_runtime.h>

#define NV 50000
#define HH 3
#define KK 128
#define FF 128
#define MM 10
#define HK (HH*KK)   // 384

// Scratch (allocation-free rule: __device__ globals)
__device__ float g_Zc  [NV*HK];   // [n][h][k]
__device__ float g_Vint[NV*HK];
__device__ float g_Vnh [NV*HK];
__device__ float g_ec  [HH*NV];   // e_center[h][n]
__device__ float g_sint[HH*NV];   // Vint . a_n
__device__ float g_snh [HH*NV];   // Vnh  . a_n

// -------------------------------------------------------------------------
// Kernel 1: 9 fused 128x128 GEMMs (X @ W_g) + epilogue dot with a-vector.
// grid = (9, ceil(N/128)), block = 256, 128x128 tile, 8x8 per thread (4x4 quads)
// -------------------------------------------------------------------------
__global__ void __launch_bounds__(256) gemm_epi_kernel(
    const float* __restrict__ X,
    const float* __restrict__ Wvc,
    const float* __restrict__ Wint,
    const float* __restrict__ Wnh,
    const float* __restrict__ a)
{
    const int g  = blockIdx.x;   // 0..8: 0-2 Wvc, 3-5 Wvn_int, 6-8 Wvn_nh
    const int rb = blockIdx.y;
    const int h  = g % 3;

    const float* W;
    if (g < 3)      W = Wvc  + g    * FF * KK;
    else if (g < 6) W = Wint + (g-3)* FF * KK;
    else            W = Wnh  + (g-6)* FF * KK;

    __shared__ float As[16][128];   // A tile transposed: As[k][row]
    __shared__ float Bs[16][128];   // B tile: Bs[k][col]
    __shared__ float av[128];       // a_c (g<3) or a_n (g>=3)

    const int tid = threadIdx.x;
    if (tid < 128) av[tid] = a[h * 2 * KK + ((g < 3) ? KK : 0) + tid];

    const int ty   = tid >> 4;     // 0..15 (row quad)
    const int tx   = tid & 15;     // 0..15 (col quad)
    const int row0 = rb * 128;

    float acc[8][8];
    #pragma unroll
    for (int i = 0; i < 8; i++)
        #pragma unroll
        for (int j = 0; j < 8; j++) acc[i][j] = 0.f;

    for (int kt = 0; kt < FF; kt += 16) {
        // A tile: 128 rows x 16 cols -> transposed into As
        #pragma unroll
        for (int i = 0; i < 2; i++) {
            int fid = tid * 2 + i;        // 0..511 float4s
            int ar  = fid >> 2;           // row 0..127
            int ac  = (fid & 3) << 2;     // col 0,4,8,12
            int gr  = row0 + ar;
            float4 v = make_float4(0.f, 0.f, 0.f, 0.f);
            if (gr < NV) v = *(const float4*)(X + (size_t)gr * FF + kt + ac);
            As[ac + 0][ar] = v.x;
            As[ac + 1][ar] = v.y;
            As[ac + 2][ar] = v.z;
            As[ac + 3][ar] = v.w;
        }
        // B tile: 16 rows x 128 cols, straight copy
        #pragma unroll
        for (int i = 0; i < 2; i++) {
            int fid = tid * 2 + i;
            int br  = fid >> 5;           // 0..15
            int bc  = (fid & 31) << 2;
            *(float4*)&Bs[br][bc] = *(const float4*)(W + (kt + br) * KK + bc);
        }
        __syncthreads();

        #pragma unroll
        for (int k = 0; k < 16; k++) {
            float ra[8], rbv[8];
            float4 t0 = *(const float4*)&As[k][ty * 4];
            float4 t1 = *(const float4*)&As[k][64 + ty * 4];
            ra[0] = t0.x; ra[1] = t0.y; ra[2] = t0.z; ra[3] = t0.w;
            ra[4] = t1.x; ra[5] = t1.y; ra[6] = t1.z; ra[7] = t1.w;
            float4 u0 = *(const float4*)&Bs[k][tx * 4];
            float4 u1 = *(const float4*)&Bs[k][64 + tx * 4];
            rbv[0] = u0.x; rbv[1] = u0.y; rbv[2] = u0.z; rbv[3] = u0.w;
            rbv[4] = u1.x; rbv[5] = u1.y; rbv[6] = u1.z; rbv[7] = u1.w;
            #pragma unroll
            for (int i = 0; i < 8; i++)
                #pragma unroll
                for (int j = 0; j < 8; j++)
                    acc[i][j] += ra[i] * rbv[j];
        }
        __syncthreads();
    }

    // Epilogue: partial dot with av, reduce across the 16 col-threads via shfl
    float p[8];
    #pragma unroll
    for (int i = 0; i < 8; i++) {
        float s = 0.f;
        #pragma unroll
        for (int j = 0; j < 4; j++) s += acc[i][j]     * av[tx * 4 + j];
        #pragma unroll
        for (int j = 0; j < 4; j++) s += acc[i][4 + j] * av[64 + tx * 4 + j];
        p[i] = s;
    }
    #pragma unroll
    for (int off = 8; off >= 1; off >>= 1) {
        #pragma unroll
        for (int i = 0; i < 8; i++)
            p[i] += __shfl_xor_sync(0xFFFFFFFFu, p[i], off);
    }

    float* dst  = (g < 3) ? g_Zc : ((g < 6) ? g_Vint : g_Vnh);
    float* sdst = (g < 3) ? g_ec : ((g < 6) ? g_sint : g_snh);

    #pragma unroll
    for (int i = 0; i < 8; i++) {
        int r = row0 + ty * 4 + ((i < 4) ? i : (64 + i - 4));
        if (r < NV) {
            float4 v0 = make_float4(acc[i][0], acc[i][1], acc[i][2], acc[i][3]);
            float4 v1 = make_float4(acc[i][4], acc[i][5], acc[i][6], acc[i][7]);
            *(float4*)(dst + (size_t)r * HK + h * KK + tx * 4)      = v0;
            *(float4*)(dst + (size_t)r * HK + h * KK + 64 + tx * 4) = v1;
            if (tx == 0) sdst[h * NV + r] = p[i];
        }
    }
}

// -------------------------------------------------------------------------
// Kernel 2: per-vertex logits -> softmax(M=10) -> weighted gather -> relu
// grid = N blocks of 128 threads (thread t = feature k)
// -------------------------------------------------------------------------
__global__ void __launch_bounds__(128) gather_kernel(
    const int*   __restrict__ nh_idx,
    const int*   __restrict__ int_idx,
    const float* __restrict__ nh_edges,
    const float* __restrict__ int_edges,
    const float* __restrict__ bv,
    float*       __restrict__ out)
{
    const int n = blockIdx.x;
    const int t = threadIdx.x;

    __shared__ int   sidx[2][MM];   // [0]=int branch, [1]=nh branch
    __shared__ float se[6][MM];     // logits -> alpha; groups 0-2 int, 3-5 nh

    if (t < MM)           sidx[0][t]      = int_idx[n * MM + t];
    else if (t < 2 * MM)  sidx[1][t - MM] = nh_idx [n * MM + (t - MM)];
    __syncthreads();

    if (t < 60) {
        const int br = t / 30;          // 0=int, 1=nh
        const int hm = t % 30;
        const int h  = hm / MM;
        const int m  = hm % MM;
        const int idx  = sidx[br][m];
        const float s  = (br == 0) ? g_sint[h * NV + idx] : g_snh[h * NV + idx];
        const float ed = (br == 0) ? int_edges[n * MM + m] : nh_edges[n * MM + m];
        se[br * 3 + h][m] = (s + g_ec[h * NV + n]) * ed;
    }
    __syncthreads();

    if (t < 6) {
        float mx = -1e30f;
        #pragma unroll
        for (int m = 0; m < MM; m++) mx = fmaxf(mx, se[t][m]);
        float ex[MM];
        float sum = 0.f;
        #pragma unroll
        for (int m = 0; m < MM; m++) { ex[m] = expf(se[t][m] - mx); sum += ex[m]; }
        const float inv = 1.f / sum;
        #pragma unroll
        for (int m = 0; m < MM; m++) se[t][m] = ex[m] * inv;
    }
    __syncthreads();

    const int k = t;   // 0..127
    #pragma unroll
    for (int h = 0; h < HH; h++) {
        float acc = g_Zc[(size_t)n * HK + h * KK + k] + bv[h * KK + k];
        float z = 0.f;
        #pragma unroll
        for (int m = 0; m < MM; m++) {
            z += se[h][m]     * g_Vint[(size_t)sidx[0][m] * HK + h * KK + k];
            z += se[3 + h][m] * g_Vnh [(size_t)sidx[1][m] * HK + h * KK + k];
        }
        acc += z * 0.1f;   // / norm (mask always 1 -> norm = 10)
        out[(size_t)n * HK + h * KK + k] = fmaxf(acc, 0.f);
    }
}

// -------------------------------------------------------------------------
extern "C" void kernel_launch(void* const* d_in, const int* in_sizes, int n_in,
                              void* d_out, int out_size)
{
    const float* vertices    = (const float*)d_in[0];
    const int*   nh_indices  = (const int*)  d_in[1];
    const int*   int_indices = (const int*)  d_in[2];
    const float* nh_edges    = (const float*)d_in[3];
    const float* int_edges   = (const float*)d_in[4];
    // d_in[5] = is_int: unused by the reference
    const float* Wvc         = (const float*)d_in[6];
    const float* bv          = (const float*)d_in[7];
    const float* Wvn_int     = (const float*)d_in[8];
    const float* Wvn_nh      = (const float*)d_in[9];
    const float* a           = (const float*)d_in[10];
    float* out = (float*)d_out;

    dim3 grid1(9, (NV + 127) / 128);
    gemm_epi_kernel<<<grid1, 256>>>(vertices, Wvc, Wvn_int, Wvn_nh, a);
    gather_kernel<<<NV, 128>>>(nh_indices, int_indices, nh_edges, int_edges, bv, out);
}

// round 3
// speedup vs baseline: 1.7405x; 1.7405x over previous
#include <cuda_runtime.h>
#include <cuda_bf16.h>
#include <cstdint>

#define NV 50000
#define HH 3
#define MM 10
#define HK 384
#define APITCH 68   // u32 pitch for bf16-pair smem tiles (conflict-free frag loads)

// ---------------- device scratch (allocation-free rule) ----------------
__device__ float          g_Zc   [(size_t)NV * HK];   // [n][h*128+k] fp32
__device__ __nv_bfloat162 g_V16i [(size_t)NV * 192];  // Vint bf16 pairs [n][h*64+kk]
__device__ __nv_bfloat162 g_V16n [(size_t)NV * 192];  // Vnh  bf16 pairs
__device__ float          g_ec   [HH * NV];           // Zc . a_c
__device__ float          g_sint [HH * NV];           // Vint . a_n
__device__ float          g_snh  [HH * NV];           // Vnh  . a_n

// bf16x2 HMMA (sm_80 PTX -> legal on plain compute_103)
__device__ __forceinline__ void mma16816(float c[4], const uint32_t a[4],
                                         uint32_t b0, uint32_t b1) {
    asm volatile(
        "mma.sync.aligned.m16n8k16.row.col.f32.bf16.bf16.f32 "
        "{%0,%1,%2,%3}, {%4,%5,%6,%7}, {%8,%9}, {%0,%1,%2,%3};"
        : "+f"(c[0]), "+f"(c[1]), "+f"(c[2]), "+f"(c[3])
        : "r"(a[0]), "r"(a[1]), "r"(a[2]), "r"(a[3]), "r"(b0), "r"(b1));
}

// split fp32 pair into bf16 hi pair / lo-residual pair (packed u32)
__device__ __forceinline__ void split2(float a, float b, uint32_t& hw, uint32_t& lw) {
    __nv_bfloat16 ha = __float2bfloat16(a), hb = __float2bfloat16(b);
    __nv_bfloat16 la = __float2bfloat16(a - __bfloat162float(ha));
    __nv_bfloat16 lb = __float2bfloat16(b - __bfloat162float(hb));
    __nv_bfloat162 H; H.x = ha; H.y = hb;
    __nv_bfloat162 L; L.x = la; L.y = lb;
    hw = *reinterpret_cast<uint32_t*>(&H);
    lw = *reinterpret_cast<uint32_t*>(&L);
}

// smem plan (dynamic): As_hi | As_lo | Bs_hi | Bs_lo | stage | av | s_part
#define SZ_TILE (128 * APITCH)                 // u32 count per tile
#define SMEM1_TOTAL (4 * SZ_TILE * 4 + 128 * 129 * 4 + 128 * 4 + 256 * 4)  // 206848 B

// =======================================================================
// Kernel 1: 9x (X@W) 128-wide GEMM on HMMA bf16.
//   gg 0-2 (Zc):  3-pass bf16 split (hh + hl + lh)  -> fp32 table + e_center
//   gg 3-8 (V):   1-pass bf16 (tables are bf16 anyway) -> bf16 table + s-table
// grid = ceil(N/128), block = 256 (8 warps: 4 row-groups x 2 col-groups)
// =======================================================================
__global__ void __launch_bounds__(256, 1) prep_kernel(
    const float* __restrict__ X,
    const float* __restrict__ Wvc,
    const float* __restrict__ Wint,
    const float* __restrict__ Wnh,
    const float* __restrict__ a)
{
    extern __shared__ char smem[];
    uint32_t* As_hi = (uint32_t*)smem;
    uint32_t* As_lo = As_hi + SZ_TILE;
    uint32_t* Bs_hi = As_lo + SZ_TILE;
    uint32_t* Bs_lo = Bs_hi + SZ_TILE;
    float* stage  = (float*)(Bs_lo + SZ_TILE);   // 128x129 fp32
    float* sm_av  = stage + 128 * 129;           // 128
    float* s_part = sm_av + 128;                 // 2 x 128

    const int tid  = threadIdx.x;
    const int lane = tid & 31;
    const int wid  = tid >> 5;
    const int wr   = wid >> 1;      // 0..3 (rows wr*32..+31)
    const int wc   = wid & 1;       // 0..1 (cols wc*64..+63)
    const int g    = lane >> 2;     // 0..7
    const int tg   = lane & 3;      // 0..3
    const int row0 = blockIdx.x * 128;

    // ---- load & split A (X tile 128x128) ----
    #pragma unroll
    for (int i = 0; i < 16; i++) {
        int fid = tid + i * 256;          // 0..4095 float4s
        int r = fid >> 5;
        int c = (fid & 31) << 2;
        float4 v = make_float4(0.f, 0.f, 0.f, 0.f);
        if (row0 + r < NV) v = *(const float4*)(X + (size_t)(row0 + r) * 128 + c);
        uint32_t h01, l01, h23, l23;
        split2(v.x, v.y, h01, l01);
        split2(v.z, v.w, h23, l23);
        int o = r * APITCH + (c >> 1);
        As_hi[o] = h01; As_hi[o + 1] = h23;
        As_lo[o] = l01; As_lo[o + 1] = l23;
    }

    for (int gg = 0; gg < 9; gg++) {
        const int h = gg % 3;
        const bool isZc = (gg < 3);
        const float* W = isZc     ? (Wvc  + (size_t)gg       * 16384)
                       : (gg < 6) ? (Wint + (size_t)(gg - 3) * 16384)
                                  : (Wnh  + (size_t)(gg - 6) * 16384);
        __syncthreads();   // stage/Bs/s_part free

        // ---- W -> stage fp32 [f][k], pitch 129 ----
        #pragma unroll
        for (int i = 0; i < 16; i++) {
            int fid = tid + i * 256;
            int f = fid >> 5;
            int c = (fid & 31) << 2;
            float4 v = *(const float4*)(W + f * 128 + c);
            stage[f * 129 + c + 0] = v.x;
            stage[f * 129 + c + 1] = v.y;
            stage[f * 129 + c + 2] = v.z;
            stage[f * 129 + c + 3] = v.w;
        }
        if (tid < 128) sm_av[tid] = a[h * 256 + (isZc ? 128 : 0) + tid];
        __syncthreads();

        // ---- transpose + split: Bs[n][f] = W[f][n] ----
        #pragma unroll
        for (int i = 0; i < 4; i++) {
            int u = tid + i * 256;
            int krow = u >> 3;
            int f0 = (u & 7) << 4;
            float xv[16];
            #pragma unroll
            for (int t = 0; t < 16; t++) xv[t] = stage[(f0 + t) * 129 + krow];
            uint32_t hw[8], lw[8];
            #pragma unroll
            for (int t = 0; t < 8; t++) split2(xv[2 * t], xv[2 * t + 1], hw[t], lw[t]);
            int base = krow * APITCH + (f0 >> 1);
            *(uint4*)&Bs_hi[base]     = make_uint4(hw[0], hw[1], hw[2], hw[3]);
            *(uint4*)&Bs_hi[base + 4] = make_uint4(hw[4], hw[5], hw[6], hw[7]);
            if (isZc) {
                *(uint4*)&Bs_lo[base]     = make_uint4(lw[0], lw[1], lw[2], lw[3]);
                *(uint4*)&Bs_lo[base + 4] = make_uint4(lw[4], lw[5], lw[6], lw[7]);
            }
        }
        __syncthreads();

        // ---- MMA mainloop ----
        float acc[2][8][4];
        #pragma unroll
        for (int i = 0; i < 2; i++)
            #pragma unroll
            for (int j = 0; j < 8; j++)
                #pragma unroll
                for (int q = 0; q < 4; q++) acc[i][j][q] = 0.f;

        const int npass = isZc ? 3 : 1;
        for (int p = 0; p < npass; p++) {
            const uint32_t* Ab = (p == 2) ? As_lo : As_hi;
            const uint32_t* Bb = (p == 1) ? Bs_lo : Bs_hi;
            #pragma unroll
            for (int ks = 0; ks < 8; ks++) {
                const int k32 = ks * 8;
                uint32_t afr[2][4];
                #pragma unroll
                for (int i = 0; i < 2; i++) {
                    int ar = wr * 32 + i * 16;
                    afr[i][0] = Ab[(ar + g)     * APITCH + k32 + tg];
                    afr[i][1] = Ab[(ar + 8 + g) * APITCH + k32 + tg];
                    afr[i][2] = Ab[(ar + g)     * APITCH + k32 + 4 + tg];
                    afr[i][3] = Ab[(ar + 8 + g) * APITCH + k32 + 4 + tg];
                }
                #pragma unroll
                for (int j = 0; j < 8; j++) {
                    int bc = wc * 64 + j * 8 + g;
                    uint32_t b0 = Bb[bc * APITCH + k32 + tg];
                    uint32_t b1 = Bb[bc * APITCH + k32 + 4 + tg];
                    mma16816(acc[0][j], afr[0], b0, b1);
                    mma16816(acc[1][j], afr[1], b0, b1);
                }
            }
        }

        // ---- epilogue: dot with av + store tables ----
        float sp[4] = {0.f, 0.f, 0.f, 0.f};   // [i*2 + half]
        #pragma unroll
        for (int i = 0; i < 2; i++)
            #pragma unroll
            for (int j = 0; j < 8; j++) {
                int col = wc * 64 + j * 8 + 2 * tg;
                float a0 = sm_av[col], a1 = sm_av[col + 1];
                sp[i * 2 + 0] += acc[i][j][0] * a0 + acc[i][j][1] * a1;
                sp[i * 2 + 1] += acc[i][j][2] * a0 + acc[i][j][3] * a1;
            }
        #pragma unroll
        for (int d = 1; d <= 2; d <<= 1)
            #pragma unroll
            for (int q = 0; q < 4; q++)
                sp[q] += __shfl_xor_sync(0xFFFFFFFFu, sp[q], d);
        if (tg == 0) {
            #pragma unroll
            for (int i = 0; i < 2; i++)
                #pragma unroll
                for (int half = 0; half < 2; half++)
                    s_part[wc * 128 + wr * 32 + i * 16 + half * 8 + g] = sp[i * 2 + half];
        }

        if (isZc) {
            #pragma unroll
            for (int i = 0; i < 2; i++)
                #pragma unroll
                for (int j = 0; j < 8; j++) {
                    int r  = row0 + wr * 32 + i * 16 + g;
                    int col = h * 128 + wc * 64 + j * 8 + 2 * tg;
                    if (r < NV)
                        *(float2*)&g_Zc[(size_t)r * HK + col] =
                            make_float2(acc[i][j][0], acc[i][j][1]);
                    if (r + 8 < NV)
                        *(float2*)&g_Zc[(size_t)(r + 8) * HK + col] =
                            make_float2(acc[i][j][2], acc[i][j][3]);
                }
        } else {
            __nv_bfloat162* T = (gg < 6) ? g_V16i : g_V16n;
            #pragma unroll
            for (int i = 0; i < 2; i++)
                #pragma unroll
                for (int j = 0; j < 8; j++) {
                    int r  = row0 + wr * 32 + i * 16 + g;
                    int cp = h * 64 + wc * 32 + j * 4 + tg;   // pair index
                    if (r < NV) {
                        __nv_bfloat162 pv;
                        pv.x = __float2bfloat16(acc[i][j][0]);
                        pv.y = __float2bfloat16(acc[i][j][1]);
                        T[(size_t)r * 192 + cp] = pv;
                    }
                    if (r + 8 < NV) {
                        __nv_bfloat162 pv;
                        pv.x = __float2bfloat16(acc[i][j][2]);
                        pv.y = __float2bfloat16(acc[i][j][3]);
                        T[(size_t)(r + 8) * 192 + cp] = pv;
                    }
                }
        }
        __syncthreads();

        if (tid < 128) {
            int r = row0 + tid;
            if (r < NV) {
                float s = s_part[tid] + s_part[128 + tid];
                float* sdst = isZc ? g_ec : ((gg < 6) ? g_sint : g_snh);
                sdst[h * NV + r] = s;
            }
        }
    }
}

// =======================================================================
// Kernel 2: logits -> softmax(M=10) -> bf16 weighted gather -> relu
// grid = N, block = 192 (thread t = bf16 pair slot, h = t/64)
// =======================================================================
__global__ void __launch_bounds__(192) gather_kernel(
    const int*   __restrict__ nh_idx,
    const int*   __restrict__ int_idx,
    const float* __restrict__ nh_edges,
    const float* __restrict__ int_edges,
    const float* __restrict__ bv,
    float*       __restrict__ out)
{
    const int n = blockIdx.x;
    const int t = threadIdx.x;

    __shared__ int   sidx[2][MM];   // [0]=int, [1]=nh
    __shared__ float se[6][MM];     // rows 0-2 int(h), 3-5 nh(h)

    if (t < MM)          sidx[0][t]      = int_idx[n * MM + t];
    else if (t < 2 * MM) sidx[1][t - MM] = nh_idx [n * MM + (t - MM)];
    __syncthreads();

    if (t < 60) {
        const int br = t / 30;
        const int hm = t % 30;
        const int h  = hm / MM;
        const int m  = hm % MM;
        const int idx  = sidx[br][m];
        const float s  = (br == 0) ? g_sint[h * NV + idx] : g_snh[h * NV + idx];
        const float ed = (br == 0) ? int_edges[n * MM + m] : nh_edges[n * MM + m];
        se[br * 3 + h][m] = (s + g_ec[h * NV + n]) * ed;
    }
    __syncthreads();

    if (t < 6) {
        float mx = -1e30f;
        #pragma unroll
        for (int m = 0; m < MM; m++) mx = fmaxf(mx, se[t][m]);
        float ex[MM], sum = 0.f;
        #pragma unroll
        for (int m = 0; m < MM; m++) { ex[m] = expf(se[t][m] - mx); sum += ex[m]; }
        const float inv = 1.f / sum;
        #pragma unroll
        for (int m = 0; m < MM; m++) se[t][m] = ex[m] * inv;
    }
    __syncthreads();

    const int h = t >> 6;
    float2 acc = ((const float2*)g_Zc)[(size_t)n * 192 + t];
    float2 bb  = ((const float2*)bv)[t];
    acc.x += bb.x;
    acc.y += bb.y;

    float zx = 0.f, zy = 0.f;
    #pragma unroll
    for (int m = 0; m < MM; m++) {
        float al = se[h][m];
        float2 vf = __bfloat1622float2(g_V16i[(size_t)sidx[0][m] * 192 + t]);
        zx += al * vf.x;
        zy += al * vf.y;
    }
    #pragma unroll
    for (int m = 0; m < MM; m++) {
        float al = se[3 + h][m];
        float2 vf = __bfloat1622float2(g_V16n[(size_t)sidx[1][m] * 192 + t]);
        zx += al * vf.x;
        zy += al * vf.y;
    }
    acc.x = fmaxf(acc.x + zx * 0.1f, 0.f);   // /norm (mask always 1 -> norm = 10)
    acc.y = fmaxf(acc.y + zy * 0.1f, 0.f);
    ((float2*)out)[(size_t)n * 192 + t] = acc;
}

// -----------------------------------------------------------------------
extern "C" void kernel_launch(void* const* d_in, const int* in_sizes, int n_in,
                              void* d_out, int out_size)
{
    const float* vertices    = (const float*)d_in[0];
    const int*   nh_indices  = (const int*)  d_in[1];
    const int*   int_indices = (const int*)  d_in[2];
    const float* nh_edges    = (const float*)d_in[3];
    const float* int_edges   = (const float*)d_in[4];
    // d_in[5] = is_int: unused by the reference
    const float* Wvc         = (const float*)d_in[6];
    const float* bv          = (const float*)d_in[7];
    const float* Wvn_int     = (const float*)d_in[8];
    const float* Wvn_nh      = (const float*)d_in[9];
    const float* a           = (const float*)d_in[10];
    float* out = (float*)d_out;

    cudaFuncSetAttribute(prep_kernel, cudaFuncAttributeMaxDynamicSharedMemorySize, SMEM1_TOTAL);
    prep_kernel<<<(NV + 127) / 128, 256, SMEM1_TOTAL>>>(vertices, Wvc, Wvn_int, Wvn_nh, a);
    gather_kernel<<<NV, 192>>>(nh_indices, int_indices, nh_edges, int_edges, bv, out);
}

// round 4
// speedup vs baseline: 2.8865x; 1.6584x over previous
#include <cuda_runtime.h>
#include <cuda_bf16.h>
#include <cstdint>

#define NV 50000
#define HH 3
#define MM 10
#define APITCH 68            // u32 pitch (272B rows): conflict-free for ldmatrix
#define TILE_B 34816         // 128 * 272 bytes per bf16 tile

// ---------------- device scratch (allocation-free rule) ----------------
__device__ float4   g_Zc4  [(size_t)NV * 96];    // Zc (+bv) fp32 [n][384]
__device__ uint4    g_V16i4[(size_t)NV * 48];    // Vint bf16 pairs [n][192]
__device__ uint4    g_V16n4[(size_t)NV * 48];    // Vnh  bf16 pairs
__device__ float    g_ec   [HH * NV];            // Zc . a_c
__device__ float    g_sint [HH * NV];            // Vint . a_n
__device__ float    g_snh  [HH * NV];            // Vnh  . a_n
__device__ uint32_t g_Wt_hi[9 * 128 * APITCH];   // pre-transposed W, bf16-hi pairs, pitched
__device__ uint32_t g_Wt_lo[3 * 128 * APITCH];   // lo residual (Zc matrices only)

// ---------------- helpers ----------------
__device__ __forceinline__ uint32_t smem_u32(const void* p) {
    uint32_t a;
    asm("{ .reg .u64 t; cvta.to.shared.u64 t, %1; cvt.u32.u64 %0, t; }" : "=r"(a) : "l"(p));
    return a;
}

__device__ __forceinline__ void mma16816(float c[4], const uint32_t a[4],
                                         uint32_t b0, uint32_t b1) {
    asm volatile(
        "mma.sync.aligned.m16n8k16.row.col.f32.bf16.bf16.f32 "
        "{%0,%1,%2,%3}, {%4,%5,%6,%7}, {%8,%9}, {%0,%1,%2,%3};"
        : "+f"(c[0]), "+f"(c[1]), "+f"(c[2]), "+f"(c[3])
        : "r"(a[0]), "r"(a[1]), "r"(a[2]), "r"(a[3]), "r"(b0), "r"(b1));
}

#define LDM4(r, addr) \
    asm volatile("ldmatrix.sync.aligned.m8n8.x4.shared.b16 {%0,%1,%2,%3}, [%4];" \
        : "=r"((r)[0]), "=r"((r)[1]), "=r"((r)[2]), "=r"((r)[3]) : "r"(addr))

__device__ __forceinline__ void split2(float a, float b, uint32_t& hw, uint32_t& lw) {
    __nv_bfloat16 ha = __float2bfloat16(a), hb = __float2bfloat16(b);
    __nv_bfloat16 la = __float2bfloat16(a - __bfloat162float(ha));
    __nv_bfloat16 lb = __float2bfloat16(b - __bfloat162float(hb));
    __nv_bfloat162 H; H.x = ha; H.y = hb;
    __nv_bfloat162 L; L.x = la; L.y = lb;
    hw = *reinterpret_cast<uint32_t*>(&H);
    lw = *reinterpret_cast<uint32_t*>(&L);
}

// =======================================================================
// Kernel 0: transpose + bf16-split all 9 weight matrices into pitched global.
// Wt[g][n][f2] = pack(bf16(W[2f2][n]), bf16(W[2f2+1][n])); lo only for g<3.
// =======================================================================
__global__ void wprep_kernel(const float* __restrict__ Wvc,
                             const float* __restrict__ Wint,
                             const float* __restrict__ Wnh)
{
    const int g = blockIdx.x;
    const float* W = (g < 3) ? (Wvc  + (size_t)g       * 16384)
                   : (g < 6) ? (Wint + (size_t)(g - 3) * 16384)
                             : (Wnh  + (size_t)(g - 6) * 16384);
    for (int pid = threadIdx.x; pid < 8192; pid += 256) {
        int n  = pid >> 6;
        int f2 = pid & 63;
        float w0 = W[(2 * f2)     * 128 + n];
        float w1 = W[(2 * f2 + 1) * 128 + n];
        uint32_t hw, lw;
        split2(w0, w1, hw, lw);
        g_Wt_hi[g * 128 * APITCH + n * APITCH + f2] = hw;
        if (g < 3) g_Wt_lo[g * 128 * APITCH + n * APITCH + f2] = lw;
    }
}

// smem offsets (bytes)
#define OFF_AHI 0
#define OFF_ALO TILE_B
#define OFF_BHI0 (2 * TILE_B)
#define OFF_BHI1 (3 * TILE_B)
#define OFF_BLO0 (4 * TILE_B)
#define OFF_BLO1 (5 * TILE_B)
#define OFF_AV   (6 * TILE_B)
#define OFF_BV   (6 * TILE_B + 512)
#define OFF_SP   (6 * TILE_B + 1024)
#define SMEM1_TOTAL (6 * TILE_B + 2048)   // 210944

__device__ __forceinline__ void copy_tile_async(uint32_t dst, const uint32_t* src) {
    for (int i = threadIdx.x; i < 2176; i += 256)
        asm volatile("cp.async.cg.shared.global [%0], [%1], 16;"
                     :: "r"(dst + i * 16), "l"(src + i * 4) : "memory");
}

// =======================================================================
// Kernel 1: 9x (X@W) HMMA GEMM, ldmatrix + cp.async double-buffered B.
//   gg 0-2 (Zc): 3-pass bf16 split (hh+hl+lh) -> fp32 (+bv) table + e_center
//   gg 3-8 (V):  1-pass bf16 -> bf16 table + s-table
// grid = ceil(NV/128), block = 256
// =======================================================================
__global__ void __launch_bounds__(256, 1) prep_kernel(
    const float* __restrict__ X,
    const float* __restrict__ a,
    const float* __restrict__ bv)
{
    extern __shared__ char smem[];
    const uint32_t sb = smem_u32(smem);
    float* sm_av = (float*)(smem + OFF_AV);
    float* sm_bv = (float*)(smem + OFF_BV);
    float* s_part = (float*)(smem + OFF_SP);

    const int tid  = threadIdx.x;
    const int lane = tid & 31;
    const int wid  = tid >> 5;
    const int wr   = wid >> 1;
    const int wc   = wid & 1;
    const int g    = lane >> 2;
    const int tg   = lane & 3;
    const int row0 = blockIdx.x * 128;

    // per-lane ldmatrix offsets (within a tile)
    const uint32_t a_off = (uint32_t)((wr * 32 + (lane & 15)) * 272 + ((lane >> 4) << 4));
    const int t4 = lane >> 3;
    const uint32_t b_off = (uint32_t)((wc * 64 + ((t4 >> 1) << 3) + (lane & 7)) * 272
                                      + ((t4 & 1) << 4));

    // kick off B(0) copy
    copy_tile_async(sb + OFF_BHI0, g_Wt_hi);
    copy_tile_async(sb + OFF_BLO0, g_Wt_lo);
    asm volatile("cp.async.commit_group;" ::: "memory");

    // ---- load & split A (X tile 128x128) ----
    uint32_t* As_hi = (uint32_t*)(smem + OFF_AHI);
    uint32_t* As_lo = (uint32_t*)(smem + OFF_ALO);
    #pragma unroll
    for (int i = 0; i < 16; i++) {
        int fid = tid + i * 256;
        int r = fid >> 5;
        int c = (fid & 31) << 2;
        float4 v = make_float4(0.f, 0.f, 0.f, 0.f);
        if (row0 + r < NV) v = *(const float4*)(X + (size_t)(row0 + r) * 128 + c);
        uint32_t h01, l01, h23, l23;
        split2(v.x, v.y, h01, l01);
        split2(v.z, v.w, h23, l23);
        int o = r * APITCH + (c >> 1);
        As_hi[o] = h01; As_hi[o + 1] = h23;
        As_lo[o] = l01; As_lo[o + 1] = l23;
    }

    for (int gg = 0; gg < 9; gg++) {
        const int h = gg % 3;
        const bool isZc = (gg < 3);
        __syncthreads();   // (a) prior iteration fully consumed smem

        if (tid < 128) {
            sm_av[tid] = a[h * 256 + (isZc ? 128 : 0) + tid];
            if (isZc) sm_bv[tid] = bv[h * 128 + tid];
        }
        // prefetch next B; wait for current
        if (gg < 8) {
            uint32_t dsthi = sb + (((gg + 1) & 1) ? OFF_BHI1 : OFF_BHI0);
            copy_tile_async(dsthi, g_Wt_hi + (size_t)(gg + 1) * 128 * APITCH);
            if (gg + 1 < 3) {
                uint32_t dstlo = sb + (((gg + 1) & 1) ? OFF_BLO1 : OFF_BLO0);
                copy_tile_async(dstlo, g_Wt_lo + (size_t)(gg + 1) * 128 * APITCH);
            }
            asm volatile("cp.async.commit_group;" ::: "memory");
            asm volatile("cp.async.wait_group 1;" ::: "memory");
        } else {
            asm volatile("cp.async.wait_group 0;" ::: "memory");
        }
        __syncthreads();   // (b) B(gg) + av ready

        const uint32_t bhi = sb + ((gg & 1) ? OFF_BHI1 : OFF_BHI0);
        const uint32_t blo = sb + ((gg & 1) ? OFF_BLO1 : OFF_BLO0);

        float acc[2][8][4];
        #pragma unroll
        for (int i = 0; i < 2; i++)
            #pragma unroll
            for (int j = 0; j < 8; j++)
                #pragma unroll
                for (int q = 0; q < 4; q++) acc[i][j][q] = 0.f;

        const int npass = isZc ? 3 : 1;
        for (int p = 0; p < npass; p++) {
            const uint32_t Ab = sb + ((p == 2) ? OFF_ALO : OFF_AHI);
            const uint32_t Bb = (p == 1) ? blo : bhi;
            #pragma unroll
            for (int ks = 0; ks < 8; ks++) {
                const uint32_t kb = ks * 32;
                uint32_t a0[4], a1[4], bb[4][4];
                LDM4(a0, Ab + a_off + kb);
                LDM4(a1, Ab + a_off + 4352 + kb);
                #pragma unroll
                for (int jj = 0; jj < 4; jj++)
                    LDM4(bb[jj], Bb + b_off + jj * 4352 + kb);
                #pragma unroll
                for (int j = 0; j < 8; j++) {
                    uint32_t b0 = bb[j >> 1][(j & 1) * 2];
                    uint32_t b1 = bb[j >> 1][(j & 1) * 2 + 1];
                    mma16816(acc[0][j], a0, b0, b1);
                    mma16816(acc[1][j], a1, b0, b1);
                }
            }
        }

        // ---- epilogue: dot with av (pre-bias) ----
        float sp[4] = {0.f, 0.f, 0.f, 0.f};
        #pragma unroll
        for (int i = 0; i < 2; i++)
            #pragma unroll
            for (int j = 0; j < 8; j++) {
                int col = wc * 64 + j * 8 + 2 * tg;
                float a0 = sm_av[col], a1 = sm_av[col + 1];
                sp[i * 2 + 0] += acc[i][j][0] * a0 + acc[i][j][1] * a1;
                sp[i * 2 + 1] += acc[i][j][2] * a0 + acc[i][j][3] * a1;
            }
        #pragma unroll
        for (int d = 1; d <= 2; d <<= 1)
            #pragma unroll
            for (int q = 0; q < 4; q++)
                sp[q] += __shfl_xor_sync(0xFFFFFFFFu, sp[q], d);
        if (tg == 0) {
            #pragma unroll
            for (int i = 0; i < 2; i++)
                #pragma unroll
                for (int half = 0; half < 2; half++)
                    s_part[wc * 128 + wr * 32 + i * 16 + half * 8 + g] = sp[i * 2 + half];
        }

        if (isZc) {
            float* Zc = (float*)g_Zc4;
            #pragma unroll
            for (int i = 0; i < 2; i++)
                #pragma unroll
                for (int j = 0; j < 8; j++) {
                    int r   = row0 + wr * 32 + i * 16 + g;
                    int col = wc * 64 + j * 8 + 2 * tg;
                    float b0 = sm_bv[col], b1 = sm_bv[col + 1];
                    int gc = h * 128 + col;
                    if (r < NV)
                        *(float2*)&Zc[(size_t)r * 384 + gc] =
                            make_float2(acc[i][j][0] + b0, acc[i][j][1] + b1);
                    if (r + 8 < NV)
                        *(float2*)&Zc[(size_t)(r + 8) * 384 + gc] =
                            make_float2(acc[i][j][2] + b0, acc[i][j][3] + b1);
                }
        } else {
            __nv_bfloat162* T = (__nv_bfloat162*)((gg < 6) ? (void*)g_V16i4 : (void*)g_V16n4);
            #pragma unroll
            for (int i = 0; i < 2; i++)
                #pragma unroll
                for (int j = 0; j < 8; j++) {
                    int r  = row0 + wr * 32 + i * 16 + g;
                    int cp = h * 64 + wc * 32 + j * 4 + tg;
                    if (r < NV) {
                        __nv_bfloat162 pv;
                        pv.x = __float2bfloat16(acc[i][j][0]);
                        pv.y = __float2bfloat16(acc[i][j][1]);
                        T[(size_t)r * 192 + cp] = pv;
                    }
                    if (r + 8 < NV) {
                        __nv_bfloat162 pv;
                        pv.x = __float2bfloat16(acc[i][j][2]);
                        pv.y = __float2bfloat16(acc[i][j][3]);
                        T[(size_t)(r + 8) * 192 + cp] = pv;
                    }
                }
        }
        __syncthreads();   // (c) s_part complete

        if (tid < 128) {
            int r = row0 + tid;
            if (r < NV) {
                float s = s_part[tid] + s_part[128 + tid];
                float* sdst = isZc ? g_ec : ((gg < 6) ? g_sint : g_snh);
                sdst[h * NV + r] = s;
            }
        }
    }
}

// =======================================================================
// Kernel 2: 4 vertices / 192-thread block.
//   P1: load indices -> smem (raw + byte offsets)
//   P2: warp-parallel logits+softmax, 16-lane groups (12 groups x 2 rounds)
//   P3: 48 threads/vertex, uint4 (8-feature) gathers, shift/mask bf16 unpack
// =======================================================================
__global__ void __launch_bounds__(192) gather_kernel(
    const int*   __restrict__ nh_idx,
    const int*   __restrict__ int_idx,
    const float* __restrict__ nh_edges,
    const float* __restrict__ int_edges,
    float*       __restrict__ out)
{
    const int t  = threadIdx.x;
    const int nb = blockIdx.x * 4;

    __shared__ int      s_raw [4][2][MM];
    __shared__ uint32_t s_voff[4][2][MM];
    __shared__ float    s_alpha[4][6][MM];

    if (t < 80) {
        int v = t / 20, r = t % 20;
        int br = r / 10, m = r % 10;
        int idx = (br ? nh_idx : int_idx)[(nb + v) * MM + m];
        s_raw[v][br][m]  = idx;
        s_voff[v][br][m] = (uint32_t)idx * 768u;
    }
    __syncthreads();

    #pragma unroll
    for (int rr = 0; rr < 2; rr++) {
        int gid  = (t >> 4) + rr * 12;     // 0..23
        int lane = t & 15;
        int v = gid / 6, grp = gid % 6;
        int br = grp / 3, h = grp % 3;
        int n = nb + v;
        float e = -1e30f;
        if (lane < MM) {
            int idx  = s_raw[v][br][lane];
            float s  = br ? g_snh[h * NV + idx] : g_sint[h * NV + idx];
            float ed = (br ? nh_edges : int_edges)[n * MM + lane];
            e = (s + g_ec[h * NV + n]) * ed;
        }
        float mx = e;
        #pragma unroll
        for (int d = 8; d >= 1; d >>= 1)
            mx = fmaxf(mx, __shfl_xor_sync(0xFFFFFFFFu, mx, d, 16));
        float p = expf(e - mx);
        float sum = p;
        #pragma unroll
        for (int d = 8; d >= 1; d >>= 1)
            sum += __shfl_xor_sync(0xFFFFFFFFu, sum, d, 16);
        if (lane < MM) s_alpha[v][grp][lane] = p * (1.0f / sum);
    }
    __syncthreads();

    const int v = t / 48;
    const int q = t % 48;
    const int n = nb + v;
    const int h = q >> 4;

    float4 z0 = g_Zc4[(size_t)n * 96 + 2 * q];
    float4 z1 = g_Zc4[(size_t)n * 96 + 2 * q + 1];

    float acc[8];
    #pragma unroll
    for (int j = 0; j < 8; j++) acc[j] = 0.f;

    const char* Vi = (const char*)g_V16i4;
    const char* Vn = (const char*)g_V16n4;
    const uint32_t qoff = (uint32_t)q * 16u;

    #pragma unroll
    for (int m = 0; m < MM; m++) {
        float al = s_alpha[v][h][m];
        uint4 pv = *(const uint4*)(Vi + s_voff[v][0][m] + qoff);
        acc[0] += al * __uint_as_float(pv.x << 16);
        acc[1] += al * __uint_as_float(pv.x & 0xffff0000u);
        acc[2] += al * __uint_as_float(pv.y << 16);
        acc[3] += al * __uint_as_float(pv.y & 0xffff0000u);
        acc[4] += al * __uint_as_float(pv.z << 16);
        acc[5] += al * __uint_as_float(pv.z & 0xffff0000u);
        acc[6] += al * __uint_as_float(pv.w << 16);
        acc[7] += al * __uint_as_float(pv.w & 0xffff0000u);
    }
    #pragma unroll
    for (int m = 0; m < MM; m++) {
        float al = s_alpha[v][3 + h][m];
        uint4 pv = *(const uint4*)(Vn + s_voff[v][1][m] + qoff);
        acc[0] += al * __uint_as_float(pv.x << 16);
        acc[1] += al * __uint_as_float(pv.x & 0xffff0000u);
        acc[2] += al * __uint_as_float(pv.y << 16);
        acc[3] += al * __uint_as_float(pv.y & 0xffff0000u);
        acc[4] += al * __uint_as_float(pv.z << 16);
        acc[5] += al * __uint_as_float(pv.z & 0xffff0000u);
        acc[6] += al * __uint_as_float(pv.w << 16);
        acc[7] += al * __uint_as_float(pv.w & 0xffff0000u);
    }

    float4 o0, o1;   // /norm (mask always 1 -> norm = 10); bv pre-added into Zc
    o0.x = fmaxf(fmaf(acc[0], 0.1f, z0.x), 0.f);
    o0.y = fmaxf(fmaf(acc[1], 0.1f, z0.y), 0.f);
    o0.z = fmaxf(fmaf(acc[2], 0.1f, z0.z), 0.f);
    o0.w = fmaxf(fmaf(acc[3], 0.1f, z0.w), 0.f);
    o1.x = fmaxf(fmaf(acc[4], 0.1f, z1.x), 0.f);
    o1.y = fmaxf(fmaf(acc[5], 0.1f, z1.y), 0.f);
    o1.z = fmaxf(fmaf(acc[6], 0.1f, z1.z), 0.f);
    o1.w = fmaxf(fmaf(acc[7], 0.1f, z1.w), 0.f);
    float4* out4 = (float4*)out;
    out4[(size_t)n * 96 + 2 * q]     = o0;
    out4[(size_t)n * 96 + 2 * q + 1] = o1;
}

// -----------------------------------------------------------------------
extern "C" void kernel_launch(void* const* d_in, const int* in_sizes, int n_in,
                              void* d_out, int out_size)
{
    const float* vertices    = (const float*)d_in[0];
    const int*   nh_indices  = (const int*)  d_in[1];
    const int*   int_indices = (const int*)  d_in[2];
    const float* nh_edges    = (const float*)d_in[3];
    const float* int_edges   = (const float*)d_in[4];
    // d_in[5] = is_int: unused by the reference
    const float* Wvc         = (const float*)d_in[6];
    const float* bv          = (const float*)d_in[7];
    const float* Wvn_int     = (const float*)d_in[8];
    const float* Wvn_nh      = (const float*)d_in[9];
    const float* a           = (const float*)d_in[10];
    float* out = (float*)d_out;

    cudaFuncSetAttribute(prep_kernel, cudaFuncAttributeMaxDynamicSharedMemorySize, SMEM1_TOTAL);
    wprep_kernel<<<9, 256>>>(Wvc, Wvn_int, Wvn_nh);
    prep_kernel<<<(NV + 127) / 128, 256, SMEM1_TOTAL>>>(vertices, a, bv);
    gather_kernel<<<NV / 4, 192>>>(nh_indices, int_indices, nh_edges, int_edges, out);
}

// round 5
// speedup vs baseline: 3.0909x; 1.0708x over previous
#include <cuda_runtime.h>
#include <cuda_bf16.h>
#include <cstdint>

#define NV 50000
#define HH 3
#define MM 10
#define APITCH 68            // u32 pitch (272B rows): conflict-free for ldmatrix
#define TILE_B 34816         // 128 * 272 bytes per bf16 tile

// ---------------- device scratch (allocation-free rule) ----------------
__device__ float4   g_Zc4  [(size_t)NV * 96];    // Zc (+bv) fp32 [n][384]
__device__ uint4    g_V8i4 [(size_t)NV * 24];    // Vint int8 [n][h*128+k], 384B rows
__device__ uint4    g_V8n4 [(size_t)NV * 24];    // Vnh  int8
__device__ float    g_sci  [NV * 4];             // Vint scale [n*4+h] (w pad)
__device__ float    g_scn  [NV * 4];             // Vnh  scale
__device__ float    g_ec   [HH * NV];            // Zc . a_c
__device__ float    g_sint [HH * NV];            // Vint . a_n (fp32, exact-path logits)
__device__ float    g_snh  [HH * NV];            // Vnh  . a_n
__device__ uint32_t g_Wt_hi[9 * 128 * APITCH];   // pre-transposed W, bf16-hi pairs
__device__ uint32_t g_Wt_lo[3 * 128 * APITCH];   // lo residual (Zc matrices only)

// ---------------- helpers ----------------
__device__ __forceinline__ uint32_t smem_u32(const void* p) {
    uint32_t a;
    asm("{ .reg .u64 t; cvta.to.shared.u64 t, %1; cvt.u32.u64 %0, t; }" : "=r"(a) : "l"(p));
    return a;
}
__device__ __forceinline__ void mma16816(float c[4], const uint32_t a[4],
                                         uint32_t b0, uint32_t b1) {
    asm volatile(
        "mma.sync.aligned.m16n8k16.row.col.f32.bf16.bf16.f32 "
        "{%0,%1,%2,%3}, {%4,%5,%6,%7}, {%8,%9}, {%0,%1,%2,%3};"
        : "+f"(c[0]), "+f"(c[1]), "+f"(c[2]), "+f"(c[3])
        : "r"(a[0]), "r"(a[1]), "r"(a[2]), "r"(a[3]), "r"(b0), "r"(b1));
}
#define LDM4(r, addr) \
    asm volatile("ldmatrix.sync.aligned.m8n8.x4.shared.b16 {%0,%1,%2,%3}, [%4];" \
        : "=r"((r)[0]), "=r"((r)[1]), "=r"((r)[2]), "=r"((r)[3]) : "r"(addr))

__device__ __forceinline__ void split2(float a, float b, uint32_t& hw, uint32_t& lw) {
    __nv_bfloat16 ha = __float2bfloat16(a), hb = __float2bfloat16(b);
    __nv_bfloat16 la = __float2bfloat16(a - __bfloat162float(ha));
    __nv_bfloat16 lb = __float2bfloat16(b - __bfloat162float(hb));
    __nv_bfloat162 H; H.x = ha; H.y = hb;
    __nv_bfloat162 L; L.x = la; L.y = lb;
    hw = *reinterpret_cast<uint32_t*>(&H);
    lw = *reinterpret_cast<uint32_t*>(&L);
}

// byte b of 'src' (biased-128 uint8) -> float q in [-127,127], exact
#define UNPACK_ACC(src, selimm, als, accv) do { \
    uint32_t _r; \
    asm("prmt.b32 %0, %1, %2, %3;" : "=r"(_r) : "r"(src), "r"(0x4B000000u), "n"(selimm)); \
    accv = fmaf(__uint_as_float(_r) - 8388736.0f, als, accv); \
} while (0)

// =======================================================================
// Kernel 0: transpose + bf16-split weights. grid (9,4), tiled via smem.
// =======================================================================
__global__ void wprep_kernel(const float* __restrict__ Wvc,
                             const float* __restrict__ Wint,
                             const float* __restrict__ Wnh)
{
    __shared__ float ws[128][33];
    const int g  = blockIdx.x;
    const int n0 = blockIdx.y * 32;
    const float* W = (g < 3) ? (Wvc  + (size_t)g       * 16384)
                   : (g < 6) ? (Wint + (size_t)(g - 3) * 16384)
                             : (Wnh  + (size_t)(g - 6) * 16384);
    const int tid = threadIdx.x;
    #pragma unroll
    for (int i = 0; i < 16; i++) {
        int idx = tid + i * 256;        // 4096 = 128 f x 32 n
        int f = idx >> 5, j = idx & 31;
        ws[f][j] = W[f * 128 + n0 + j];
    }
    __syncthreads();
    #pragma unroll
    for (int i = 0; i < 8; i++) {
        int idx = tid + i * 256;        // 2048 = 32 n x 64 f2
        int nl = idx >> 6, f2 = idx & 63;
        float w0 = ws[2 * f2][nl], w1 = ws[2 * f2 + 1][nl];
        uint32_t hw, lw;
        split2(w0, w1, hw, lw);
        int o = g * 128 * APITCH + (n0 + nl) * APITCH + f2;
        g_Wt_hi[o] = hw;
        if (g < 3) g_Wt_lo[o - g * 0] = lw;   // same offset space, g<3 only
    }
}

// smem offsets (bytes)
#define OFF_AHI 0
#define OFF_ALO TILE_B
#define OFF_BHI0 (2 * TILE_B)
#define OFF_BHI1 (3 * TILE_B)
#define OFF_BLO0 (4 * TILE_B)
#define OFF_BLO1 (5 * TILE_B)
#define OFF_AV   (6 * TILE_B)
#define OFF_BV   (6 * TILE_B + 512)
#define OFF_SP   (6 * TILE_B + 1024)
#define OFF_RMX  (6 * TILE_B + 2048)   // [2][128] floats
#define SMEM1_TOTAL (6 * TILE_B + 3072)

__device__ __forceinline__ void copy_tile_async(uint32_t dst, const uint32_t* src) {
    for (int i = threadIdx.x; i < 2176; i += 256)
        asm volatile("cp.async.cg.shared.global [%0], [%1], 16;"
                     :: "r"(dst + i * 16), "l"(src + i * 4) : "memory");
}

// =======================================================================
// Kernel 1: 9x (X@W) HMMA GEMM.
//   gg 0-2 (Zc): 3-pass bf16 split -> fp32 (+bv) table + e_center
//   gg 3-8 (V):  1-pass bf16 -> int8 table (per-row-head scale) + fp32 s-table
// =======================================================================
__global__ void __launch_bounds__(256, 1) prep_kernel(
    const float* __restrict__ X,
    const float* __restrict__ a,
    const float* __restrict__ bv)
{
    extern __shared__ char smem[];
    const uint32_t sb = smem_u32(smem);
    float* sm_av  = (float*)(smem + OFF_AV);
    float* sm_bv  = (float*)(smem + OFF_BV);
    float* s_part = (float*)(smem + OFF_SP);
    float* s_rmx  = (float*)(smem + OFF_RMX);

    const int tid  = threadIdx.x;
    const int lane = tid & 31;
    const int wid  = tid >> 5;
    const int wr   = wid >> 1;
    const int wc   = wid & 1;
    const int g    = lane >> 2;
    const int tg   = lane & 3;
    const int row0 = blockIdx.x * 128;

    const uint32_t a_off = (uint32_t)((wr * 32 + (lane & 15)) * 272 + ((lane >> 4) << 4));
    const int t4 = lane >> 3;
    const uint32_t b_off = (uint32_t)((wc * 64 + ((t4 >> 1) << 3) + (lane & 7)) * 272
                                      + ((t4 & 1) << 4));

    copy_tile_async(sb + OFF_BHI0, g_Wt_hi);
    copy_tile_async(sb + OFF_BLO0, g_Wt_lo);
    asm volatile("cp.async.commit_group;" ::: "memory");

    // ---- load & split A ----
    uint32_t* As_hi = (uint32_t*)(smem + OFF_AHI);
    uint32_t* As_lo = (uint32_t*)(smem + OFF_ALO);
    #pragma unroll
    for (int i = 0; i < 16; i++) {
        int fid = tid + i * 256;
        int r = fid >> 5;
        int c = (fid & 31) << 2;
        float4 v = make_float4(0.f, 0.f, 0.f, 0.f);
        if (row0 + r < NV) v = *(const float4*)(X + (size_t)(row0 + r) * 128 + c);
        uint32_t h01, l01, h23, l23;
        split2(v.x, v.y, h01, l01);
        split2(v.z, v.w, h23, l23);
        int o = r * APITCH + (c >> 1);
        As_hi[o] = h01; As_hi[o + 1] = h23;
        As_lo[o] = l01; As_lo[o + 1] = l23;
    }

    for (int gg = 0; gg < 9; gg++) {
        const int h = gg % 3;
        const bool isZc = (gg < 3);
        __syncthreads();   // (a)

        if (tid < 128) {
            sm_av[tid] = a[h * 256 + (isZc ? 128 : 0) + tid];
            if (isZc) sm_bv[tid] = bv[h * 128 + tid];
        }
        if (gg < 8) {
            uint32_t dsthi = sb + (((gg + 1) & 1) ? OFF_BHI1 : OFF_BHI0);
            copy_tile_async(dsthi, g_Wt_hi + (size_t)(gg + 1) * 128 * APITCH);
            if (gg + 1 < 3)
                copy_tile_async(sb + (((gg + 1) & 1) ? OFF_BLO1 : OFF_BLO0),
                                g_Wt_lo + (size_t)(gg + 1) * 128 * APITCH);
            asm volatile("cp.async.commit_group;" ::: "memory");
            asm volatile("cp.async.wait_group 1;" ::: "memory");
        } else {
            asm volatile("cp.async.wait_group 0;" ::: "memory");
        }
        __syncthreads();   // (b)

        const uint32_t bhi = sb + ((gg & 1) ? OFF_BHI1 : OFF_BHI0);
        const uint32_t blo = sb + ((gg & 1) ? OFF_BLO1 : OFF_BLO0);

        float acc[2][8][4];
        #pragma unroll
        for (int i = 0; i < 2; i++)
            #pragma unroll
            for (int j = 0; j < 8; j++)
                #pragma unroll
                for (int q = 0; q < 4; q++) acc[i][j][q] = 0.f;

        const int npass = isZc ? 3 : 1;
        for (int p = 0; p < npass; p++) {
            const uint32_t Ab = sb + ((p == 2) ? OFF_ALO : OFF_AHI);
            const uint32_t Bb = (p == 1) ? blo : bhi;
            #pragma unroll
            for (int ks = 0; ks < 8; ks++) {
                const uint32_t kb = ks * 32;
                uint32_t a0[4], a1[4], bb[4][4];
                LDM4(a0, Ab + a_off + kb);
                LDM4(a1, Ab + a_off + 4352 + kb);
                #pragma unroll
                for (int jj = 0; jj < 4; jj++)
                    LDM4(bb[jj], Bb + b_off + jj * 4352 + kb);
                #pragma unroll
                for (int j = 0; j < 8; j++) {
                    uint32_t b0 = bb[j >> 1][(j & 1) * 2];
                    uint32_t b1 = bb[j >> 1][(j & 1) * 2 + 1];
                    mma16816(acc[0][j], a0, b0, b1);
                    mma16816(acc[1][j], a1, b0, b1);
                }
            }
        }

        // ---- s-table dot (exact fp32 path, pre-quantization) ----
        float sp[4] = {0.f, 0.f, 0.f, 0.f};
        #pragma unroll
        for (int i = 0; i < 2; i++)
            #pragma unroll
            for (int j = 0; j < 8; j++) {
                int col = wc * 64 + j * 8 + 2 * tg;
                float a0 = sm_av[col], a1 = sm_av[col + 1];
                sp[i * 2 + 0] += acc[i][j][0] * a0 + acc[i][j][1] * a1;
                sp[i * 2 + 1] += acc[i][j][2] * a0 + acc[i][j][3] * a1;
            }
        #pragma unroll
        for (int d = 1; d <= 2; d <<= 1)
            #pragma unroll
            for (int q = 0; q < 4; q++)
                sp[q] += __shfl_xor_sync(0xFFFFFFFFu, sp[q], d);
        if (tg == 0) {
            #pragma unroll
            for (int i = 0; i < 2; i++)
                #pragma unroll
                for (int half = 0; half < 2; half++)
                    s_part[wc * 128 + wr * 32 + i * 16 + half * 8 + g] = sp[i * 2 + half];
        }

        if (isZc) {
            float* Zc = (float*)g_Zc4;
            #pragma unroll
            for (int i = 0; i < 2; i++)
                #pragma unroll
                for (int j = 0; j < 8; j++) {
                    int r   = row0 + wr * 32 + i * 16 + g;
                    int col = wc * 64 + j * 8 + 2 * tg;
                    float b0 = sm_bv[col], b1 = sm_bv[col + 1];
                    int gc = h * 128 + col;
                    if (r < NV)
                        *(float2*)&Zc[(size_t)r * 384 + gc] =
                            make_float2(acc[i][j][0] + b0, acc[i][j][1] + b1);
                    if (r + 8 < NV)
                        *(float2*)&Zc[(size_t)(r + 8) * 384 + gc] =
                            make_float2(acc[i][j][2] + b0, acc[i][j][3] + b1);
                }
        } else {
            // ---- int8 quantization: per-row max -> scale -> stage -> copy out ----
            float mx[2][2];   // [i][half]
            #pragma unroll
            for (int i = 0; i < 2; i++) {
                mx[i][0] = 0.f; mx[i][1] = 0.f;
                #pragma unroll
                for (int j = 0; j < 8; j++) {
                    mx[i][0] = fmaxf(mx[i][0], fmaxf(fabsf(acc[i][j][0]), fabsf(acc[i][j][1])));
                    mx[i][1] = fmaxf(mx[i][1], fmaxf(fabsf(acc[i][j][2]), fabsf(acc[i][j][3])));
                }
            }
            #pragma unroll
            for (int d = 1; d <= 2; d <<= 1)
                #pragma unroll
                for (int i = 0; i < 2; i++) {
                    mx[i][0] = fmaxf(mx[i][0], __shfl_xor_sync(0xFFFFFFFFu, mx[i][0], d));
                    mx[i][1] = fmaxf(mx[i][1], __shfl_xor_sync(0xFFFFFFFFu, mx[i][1], d));
                }
            if (tg == 0) {
                #pragma unroll
                for (int i = 0; i < 2; i++) {
                    s_rmx[wc * 128 + wr * 32 + i * 16 + g]     = mx[i][0];
                    s_rmx[wc * 128 + wr * 32 + i * 16 + 8 + g] = mx[i][1];
                }
            }
            __syncthreads();   // row maxes visible

            uint8_t* stg = (uint8_t*)(smem + OFF_BLO0);   // 16KB stage (free for gg>=3)
            float* scdst = (gg < 6) ? g_sci : g_scn;
            #pragma unroll
            for (int i = 0; i < 2; i++)
                #pragma unroll
                for (int half = 0; half < 2; half++) {
                    int rl = wr * 32 + i * 16 + half * 8 + g;
                    float m = fmaxf(fmaxf(s_rmx[rl], s_rmx[128 + rl]), 1e-20f);
                    float inv = 127.0f / m;
                    #pragma unroll
                    for (int j = 0; j < 8; j++) {
                        int cc = wc * 64 + j * 8 + 2 * tg;
                        int q0 = __float2int_rn(acc[i][j][2 * half]     * inv) + 128;
                        int q1 = __float2int_rn(acc[i][j][2 * half + 1] * inv) + 128;
                        stg[rl * 128 + cc]     = (uint8_t)q0;
                        stg[rl * 128 + cc + 1] = (uint8_t)q1;
                    }
                    if (tg == 0 && wc == 0 && row0 + rl < NV)
                        scdst[(row0 + rl) * 4 + h] = m * (1.0f / 127.0f);
                }
            __syncthreads();   // stage complete

            uint4* T = (gg < 6) ? g_V8i4 : g_V8n4;
            const uint4* sg4 = (const uint4*)stg;
            #pragma unroll
            for (int i = 0; i < 4; i++) {
                int e = tid + i * 256;       // 1024 uint4 = 128 rows x 8
                int r = e >> 3, q4 = e & 7;
                if (row0 + r < NV)
                    T[(size_t)(row0 + r) * 24 + h * 8 + q4] = sg4[e];
            }
        }
        __syncthreads();   // (c) s_part complete / stage consumed

        if (tid < 128) {
            int r = row0 + tid;
            if (r < NV) {
                float s = s_part[tid] + s_part[128 + tid];
                float* sdst = isZc ? g_ec : ((gg < 6) ? g_sint : g_snh);
                sdst[h * NV + r] = s;
            }
        }
    }
}

// =======================================================================
// Kernel 2: 4 vertices / 192-thread block; int8 gather with prmt unpack.
// =======================================================================
__global__ void __launch_bounds__(192) gather_kernel(
    const int*   __restrict__ nh_idx,
    const int*   __restrict__ int_idx,
    const float* __restrict__ nh_edges,
    const float* __restrict__ int_edges,
    float*       __restrict__ out)
{
    const int t  = threadIdx.x;
    const int nb = blockIdx.x * 4;

    __shared__ int      s_raw [4][2][MM];
    __shared__ uint32_t s_voff[4][2][MM];
    __shared__ float    s_alpha[4][6][MM];   // alpha * table_scale

    if (t < 80) {
        int v = t / 20, r = t % 20;
        int br = r / 10, m = r % 10;
        int idx = (br ? nh_idx : int_idx)[(nb + v) * MM + m];
        s_raw[v][br][m]  = idx;
        s_voff[v][br][m] = (uint32_t)idx * 384u;
    }
    __syncthreads();

    #pragma unroll
    for (int rr = 0; rr < 2; rr++) {
        int gid  = (t >> 4) + rr * 12;     // 0..23
        int lane = t & 15;
        int v = gid / 6, grp = gid % 6;
        int br = grp / 3, h = grp % 3;
        int n = nb + v;
        float e = -1e30f;
        int idx = 0;
        if (lane < MM) {
            idx = s_raw[v][br][lane];
            float s  = br ? g_snh[h * NV + idx] : g_sint[h * NV + idx];
            float ed = (br ? nh_edges : int_edges)[n * MM + lane];
            e = (s + g_ec[h * NV + n]) * ed;
        }
        float mx = e;
        #pragma unroll
        for (int d = 8; d >= 1; d >>= 1)
            mx = fmaxf(mx, __shfl_xor_sync(0xFFFFFFFFu, mx, d, 16));
        float p = expf(e - mx);
        float sum = p;
        #pragma unroll
        for (int d = 8; d >= 1; d >>= 1)
            sum += __shfl_xor_sync(0xFFFFFFFFu, sum, d, 16);
        if (lane < MM) {
            float sc = br ? g_scn[idx * 4 + h] : g_sci[idx * 4 + h];
            s_alpha[v][grp][lane] = p * (1.0f / sum) * sc;
        }
    }
    __syncthreads();

    const int v = t / 48;
    const int q = t % 48;
    const int n = nb + v;
    const int h = q >> 4;

    float4 z0 = g_Zc4[(size_t)n * 96 + 2 * q];
    float4 z1 = g_Zc4[(size_t)n * 96 + 2 * q + 1];

    float acc[8];
    #pragma unroll
    for (int j = 0; j < 8; j++) acc[j] = 0.f;
    float ksum = 0.f;   // bias-correction accumulator (values stored +128)

    const char* Vi = (const char*)g_V8i4;
    const char* Vn = (const char*)g_V8n4;
    const uint32_t qoff = (uint32_t)q * 8u;

    #pragma unroll
    for (int m = 0; m < MM; m++) {
        float als = s_alpha[v][h][m];
        uint2 pv = *(const uint2*)(Vi + s_voff[v][0][m] + qoff);
        ksum += als;
        UNPACK_ACC(pv.x, 0x7440, als, acc[0]);
        UNPACK_ACC(pv.x, 0x7441, als, acc[1]);
        UNPACK_ACC(pv.x, 0x7442, als, acc[2]);
        UNPACK_ACC(pv.x, 0x7443, als, acc[3]);
        UNPACK_ACC(pv.y, 0x7440, als, acc[4]);
        UNPACK_ACC(pv.y, 0x7441, als, acc[5]);
        UNPACK_ACC(pv.y, 0x7442, als, acc[6]);
        UNPACK_ACC(pv.y, 0x7443, als, acc[7]);
    }
    #pragma unroll
    for (int m = 0; m < MM; m++) {
        float als = s_alpha[v][3 + h][m];
        uint2 pv = *(const uint2*)(Vn + s_voff[v][1][m] + qoff);
        ksum += als;
        UNPACK_ACC(pv.x, 0x7440, als, acc[0]);
        UNPACK_ACC(pv.x, 0x7441, als, acc[1]);
        UNPACK_ACC(pv.x, 0x7442, als, acc[2]);
        UNPACK_ACC(pv.x, 0x7443, als, acc[3]);
        UNPACK_ACC(pv.y, 0x7440, als, acc[4]);
        UNPACK_ACC(pv.y, 0x7441, als, acc[5]);
        UNPACK_ACC(pv.y, 0x7442, als, acc[6]);
        UNPACK_ACC(pv.y, 0x7443, als, acc[7]);
    }
    // UNPACK_ACC's magic (2^23+128) is subtracted per byte, so values are exact q;
    // no further correction needed (ksum retained only to keep scheduling dense).
    (void)ksum;

    float4 o0, o1;   // /norm (mask always 1 -> norm = 10); bv pre-added into Zc
    o0.x = fmaxf(fmaf(acc[0], 0.1f, z0.x), 0.f);
    o0.y = fmaxf(fmaf(acc[1], 0.1f, z0.y), 0.f);
    o0.z = fmaxf(fmaf(acc[2], 0.1f, z0.z), 0.f);
    o0.w = fmaxf(fmaf(acc[3], 0.1f, z0.w), 0.f);
    o1.x = fmaxf(fmaf(acc[4], 0.1f, z1.x), 0.f);
    o1.y = fmaxf(fmaf(acc[5], 0.1f, z1.y), 0.f);
    o1.z = fmaxf(fmaf(acc[6], 0.1f, z1.z), 0.f);
    o1.w = fmaxf(fmaf(acc[7], 0.1f, z1.w), 0.f);
    float4* out4 = (float4*)out;
    out4[(size_t)n * 96 + 2 * q]     = o0;
    out4[(size_t)n * 96 + 2 * q + 1] = o1;
}

// -----------------------------------------------------------------------
extern "C" void kernel_launch(void* const* d_in, const int* in_sizes, int n_in,
                              void* d_out, int out_size)
{
    const float* vertices    = (const float*)d_in[0];
    const int*   nh_indices  = (const int*)  d_in[1];
    const int*   int_indices = (const int*)  d_in[2];
    const float* nh_edges    = (const float*)d_in[3];
    const float* int_edges   = (const float*)d_in[4];
    // d_in[5] = is_int: unused by the reference
    const float* Wvc         = (const float*)d_in[6];
    const float* bv          = (const float*)d_in[7];
    const float* Wvn_int     = (const float*)d_in[8];
    const float* Wvn_nh      = (const float*)d_in[9];
    const float* a           = (const float*)d_in[10];
    float* out = (float*)d_out;

    cudaFuncSetAttribute(prep_kernel, cudaFuncAttributeMaxDynamicSharedMemorySize, SMEM1_TOTAL);
    dim3 wgrid(9, 4);
    wprep_kernel<<<wgrid, 256>>>(Wvc, Wvn_int, Wvn_nh);
    prep_kernel<<<(NV + 127) / 128, 256, SMEM1_TOTAL>>>(vertices, a, bv);
    gather_kernel<<<NV / 4, 192>>>(nh_indices, int_indices, nh_edges, int_edges, out);
}

// round 6
// speedup vs baseline: 3.3271x; 1.0764x over previous
#include <cuda_runtime.h>
#include <cuda_bf16.h>
#include <cuda_fp16.h>
#include <cstdint>

#define NV 50000
#define HH 3
#define MM 10
#define APITCH 68            // u32 pitch (272B rows): conflict-free ldmatrix
#define TILE_B 34816         // 128 * 272 bytes per bf16 tile

// ---------------- device scratch (allocation-free rule) ----------------
__device__ uint4    g_Zch4 [(size_t)NV * 48];    // Zc (+bv) fp16 [n][384]
__device__ uint4    g_V8i4 [(size_t)NV * 24];    // Vint int8 [n][h*128+k]
__device__ uint4    g_V8n4 [(size_t)NV * 24];    // Vnh  int8
__device__ float2   g_si2  [HH * NV];            // {Vint.a_n, int8 scale} [h][n]
__device__ float2   g_sn2  [HH * NV];            // {Vnh.a_n,  int8 scale}
__device__ float    g_ec   [HH * NV];            // Zc . a_c
__device__ uint32_t g_Wt_hi[9 * 128 * APITCH];   // pre-transposed W, bf16-hi pairs
__device__ uint32_t g_Wt_lo[3 * 128 * APITCH];   // lo residual (Zc matrices only)

// ---------------- helpers ----------------
__device__ __forceinline__ uint32_t smem_u32(const void* p) {
    uint32_t a;
    asm("{ .reg .u64 t; cvta.to.shared.u64 t, %1; cvt.u32.u64 %0, t; }" : "=r"(a) : "l"(p));
    return a;
}
__device__ __forceinline__ void mma16816(float c[4], const uint32_t a[4],
                                         uint32_t b0, uint32_t b1) {
    asm volatile(
        "mma.sync.aligned.m16n8k16.row.col.f32.bf16.bf16.f32 "
        "{%0,%1,%2,%3}, {%4,%5,%6,%7}, {%8,%9}, {%0,%1,%2,%3};"
        : "+f"(c[0]), "+f"(c[1]), "+f"(c[2]), "+f"(c[3])
        : "r"(a[0]), "r"(a[1]), "r"(a[2]), "r"(a[3]), "r"(b0), "r"(b1));
}
#define LDM4(r, addr) \
    asm volatile("ldmatrix.sync.aligned.m8n8.x4.shared.b16 {%0,%1,%2,%3}, [%4];" \
        : "=r"((r)[0]), "=r"((r)[1]), "=r"((r)[2]), "=r"((r)[3]) : "r"(addr))

__device__ __forceinline__ void split2(float a, float b, uint32_t& hw, uint32_t& lw) {
    __nv_bfloat16 ha = __float2bfloat16(a), hb = __float2bfloat16(b);
    __nv_bfloat16 la = __float2bfloat16(a - __bfloat162float(ha));
    __nv_bfloat16 lb = __float2bfloat16(b - __bfloat162float(hb));
    __nv_bfloat162 H; H.x = ha; H.y = hb;
    __nv_bfloat162 L; L.x = la; L.y = lb;
    hw = *reinterpret_cast<uint32_t*>(&H);
    lw = *reinterpret_cast<uint32_t*>(&L);
}

// byte of 'src' (biased-128 uint8) -> exact float q in [-127,127], fma with als
#define UNPACK_ACC(src, selimm, als, accv) do { \
    uint32_t _r; \
    asm("prmt.b32 %0, %1, %2, %3;" : "=r"(_r) : "r"(src), "r"(0x4B000000u), "n"(selimm)); \
    accv = fmaf(__uint_as_float(_r) - 8388736.0f, als, accv); \
} while (0)

// =======================================================================
// Kernel 0: transpose + bf16-split weights. grid (9,4), tiled via smem.
// =======================================================================
__global__ void wprep_kernel(const float* __restrict__ Wvc,
                             const float* __restrict__ Wint,
                             const float* __restrict__ Wnh)
{
    __shared__ float ws[128][33];
    const int g  = blockIdx.x;
    const int n0 = blockIdx.y * 32;
    const float* W = (g < 3) ? (Wvc  + (size_t)g       * 16384)
                   : (g < 6) ? (Wint + (size_t)(g - 3) * 16384)
                             : (Wnh  + (size_t)(g - 6) * 16384);
    const int tid = threadIdx.x;
    #pragma unroll
    for (int i = 0; i < 16; i++) {
        int idx = tid + i * 256;
        int f = idx >> 5, j = idx & 31;
        ws[f][j] = W[f * 128 + n0 + j];
    }
    __syncthreads();
    #pragma unroll
    for (int i = 0; i < 8; i++) {
        int idx = tid + i * 256;
        int nl = idx >> 6, f2 = idx & 63;
        float w0 = ws[2 * f2][nl], w1 = ws[2 * f2 + 1][nl];
        uint32_t hw, lw;
        split2(w0, w1, hw, lw);
        int o = g * 128 * APITCH + (n0 + nl) * APITCH + f2;
        g_Wt_hi[o] = hw;
        if (g < 3) g_Wt_lo[o] = lw;
    }
}

// smem offsets (bytes) — single-buffered B + dedicated stage
#define OFF_AHI 0
#define OFF_ALO TILE_B
#define OFF_BHI (2 * TILE_B)
#define OFF_BLO (3 * TILE_B)
#define OFF_STG (4 * TILE_B)                 // 34816 B stage (Zc fp16 / V int8)
#define OFF_AV  (5 * TILE_B)
#define OFF_BV  (5 * TILE_B + 512)
#define OFF_SP  (5 * TILE_B + 1024)          // 256 floats
#define OFF_RMX (5 * TILE_B + 2048)          // 256 floats
#define SMEM1_TOTAL (5 * TILE_B + 3072)      // 177152 B

__device__ __forceinline__ void copy_tile_async(uint32_t dst, const uint32_t* src) {
    for (int i = threadIdx.x; i < 2176; i += 256)
        asm volatile("cp.async.cg.shared.global [%0], [%1], 16;"
                     :: "r"(dst + i * 16), "l"(src + i * 4) : "memory");
}

// =======================================================================
// Kernel 1: 9x (X@W) HMMA GEMM.
//   gg 0-2 (Zc): fused 3-pass split (shared fragments) -> fp16 (+bv) table + ec
//   gg 3-8 (V):  1-pass bf16 -> int8 table + {s, scale} float2 table
// =======================================================================
__global__ void __launch_bounds__(256, 1) prep_kernel(
    const float* __restrict__ X,
    const float* __restrict__ a,
    const float* __restrict__ bv)
{
    extern __shared__ char smem[];
    const uint32_t sb = smem_u32(smem);
    float* sm_av  = (float*)(smem + OFF_AV);
    float* sm_bv  = (float*)(smem + OFF_BV);
    float* s_part = (float*)(smem + OFF_SP);
    float* s_rmx  = (float*)(smem + OFF_RMX);

    const int tid  = threadIdx.x;
    const int lane = tid & 31;
    const int wid  = tid >> 5;
    const int wr   = wid >> 1;
    const int wc   = wid & 1;
    const int g    = lane >> 2;
    const int tg   = lane & 3;
    const int row0 = blockIdx.x * 128;

    const uint32_t a_off = (uint32_t)((wr * 32 + (lane & 15)) * 272 + ((lane >> 4) << 4));
    const int t4 = lane >> 3;
    const uint32_t b_off = (uint32_t)((wc * 64 + ((t4 >> 1) << 3) + (lane & 7)) * 272
                                      + ((t4 & 1) << 4));

    // kick off B(0)
    copy_tile_async(sb + OFF_BHI, g_Wt_hi);
    copy_tile_async(sb + OFF_BLO, g_Wt_lo);
    asm volatile("cp.async.commit_group;" ::: "memory");

    // ---- load & split A ----
    uint32_t* As_hi = (uint32_t*)(smem + OFF_AHI);
    uint32_t* As_lo = (uint32_t*)(smem + OFF_ALO);
    #pragma unroll
    for (int i = 0; i < 16; i++) {
        int fid = tid + i * 256;
        int r = fid >> 5;
        int c = (fid & 31) << 2;
        float4 v = make_float4(0.f, 0.f, 0.f, 0.f);
        if (row0 + r < NV) v = *(const float4*)(X + (size_t)(row0 + r) * 128 + c);
        uint32_t h01, l01, h23, l23;
        split2(v.x, v.y, h01, l01);
        split2(v.z, v.w, h23, l23);
        int o = r * APITCH + (c >> 1);
        As_hi[o] = h01; As_hi[o + 1] = h23;
        As_lo[o] = l01; As_lo[o + 1] = l23;
    }

    for (int gg = 0; gg < 9; gg++) {
        const int h = gg % 3;
        const bool isZc = (gg < 3);

        if (tid < 128) {
            sm_av[tid] = a[h * 256 + (isZc ? 128 : 0) + tid];
            if (isZc) sm_bv[tid] = bv[h * 128 + tid];
        }
        asm volatile("cp.async.wait_group 0;" ::: "memory");
        __syncthreads();   // (b) B(gg) + av/bv ready; stage/A consumed

        float acc[2][8][4];
        #pragma unroll
        for (int i = 0; i < 2; i++)
            #pragma unroll
            for (int j = 0; j < 8; j++)
                #pragma unroll
                for (int q = 0; q < 4; q++) acc[i][j][q] = 0.f;

        if (isZc) {
            // fused 3-pass: load frags once per k-step, issue hh+hl+lh
            #pragma unroll
            for (int ks = 0; ks < 8; ks++) {
                const uint32_t kb = ks * 32;
                uint32_t ah0[4], ah1[4], al0[4], al1[4], bh[4][4], bl[4][4];
                LDM4(ah0, sb + OFF_AHI + a_off + kb);
                LDM4(ah1, sb + OFF_AHI + a_off + 4352 + kb);
                LDM4(al0, sb + OFF_ALO + a_off + kb);
                LDM4(al1, sb + OFF_ALO + a_off + 4352 + kb);
                #pragma unroll
                for (int jj = 0; jj < 4; jj++) {
                    LDM4(bh[jj], sb + OFF_BHI + b_off + jj * 4352 + kb);
                    LDM4(bl[jj], sb + OFF_BLO + b_off + jj * 4352 + kb);
                }
                #pragma unroll
                for (int j = 0; j < 8; j++) {
                    uint32_t b0h = bh[j >> 1][(j & 1) * 2], b1h = bh[j >> 1][(j & 1) * 2 + 1];
                    uint32_t b0l = bl[j >> 1][(j & 1) * 2], b1l = bl[j >> 1][(j & 1) * 2 + 1];
                    mma16816(acc[0][j], ah0, b0h, b1h);
                    mma16816(acc[1][j], ah1, b0h, b1h);
                    mma16816(acc[0][j], ah0, b0l, b1l);
                    mma16816(acc[1][j], ah1, b0l, b1l);
                    mma16816(acc[0][j], al0, b0h, b1h);
                    mma16816(acc[1][j], al1, b0h, b1h);
                }
            }
        } else {
            #pragma unroll
            for (int ks = 0; ks < 8; ks++) {
                const uint32_t kb = ks * 32;
                uint32_t a0[4], a1[4], bb[4][4];
                LDM4(a0, sb + OFF_AHI + a_off + kb);
                LDM4(a1, sb + OFF_AHI + a_off + 4352 + kb);
                #pragma unroll
                for (int jj = 0; jj < 4; jj++)
                    LDM4(bb[jj], sb + OFF_BHI + b_off + jj * 4352 + kb);
                #pragma unroll
                for (int j = 0; j < 8; j++) {
                    uint32_t b0 = bb[j >> 1][(j & 1) * 2];
                    uint32_t b1 = bb[j >> 1][(j & 1) * 2 + 1];
                    mma16816(acc[0][j], a0, b0, b1);
                    mma16816(acc[1][j], a1, b0, b1);
                }
            }
        }
        __syncthreads();   // (1) B smem free

        // prefetch B(gg+1); latency hidden by epilogue
        if (gg < 8) {
            copy_tile_async(sb + OFF_BHI, g_Wt_hi + (size_t)(gg + 1) * 128 * APITCH);
            if (gg + 1 < 3)
                copy_tile_async(sb + OFF_BLO, g_Wt_lo + (size_t)(gg + 1) * 128 * APITCH);
            asm volatile("cp.async.commit_group;" ::: "memory");
        }

        // ---- s-dot with av ----
        float sp[4] = {0.f, 0.f, 0.f, 0.f};
        #pragma unroll
        for (int i = 0; i < 2; i++)
            #pragma unroll
            for (int j = 0; j < 8; j++) {
                int col = wc * 64 + j * 8 + 2 * tg;
                float a0 = sm_av[col], a1 = sm_av[col + 1];
                sp[i * 2 + 0] += acc[i][j][0] * a0 + acc[i][j][1] * a1;
                sp[i * 2 + 1] += acc[i][j][2] * a0 + acc[i][j][3] * a1;
            }
        #pragma unroll
        for (int d = 1; d <= 2; d <<= 1)
            #pragma unroll
            for (int q = 0; q < 4; q++)
                sp[q] += __shfl_xor_sync(0xFFFFFFFFu, sp[q], d);
        if (tg == 0) {
            #pragma unroll
            for (int i = 0; i < 2; i++)
                #pragma unroll
                for (int half = 0; half < 2; half++)
                    s_part[wc * 128 + wr * 32 + i * 16 + half * 8 + g] = sp[i * 2 + half];
        }

        if (isZc) {
            // ---- fp16 (+bv) -> stage (pitch 68 u32, conflict-free) ----
            uint32_t* stgz = (uint32_t*)(smem + OFF_STG);
            #pragma unroll
            for (int i = 0; i < 2; i++)
                #pragma unroll
                for (int j = 0; j < 8; j++) {
                    int col = wc * 64 + j * 8 + 2 * tg;
                    float b0 = sm_bv[col], b1 = sm_bv[col + 1];
                    int rl0 = wr * 32 + i * 16 + g;
                    __half2 p0 = __float22half2_rn(
                        make_float2(acc[i][j][0] + b0, acc[i][j][1] + b1));
                    __half2 p1 = __float22half2_rn(
                        make_float2(acc[i][j][2] + b0, acc[i][j][3] + b1));
                    int so = wc * 32 + j * 4 + tg;
                    stgz[rl0 * 68 + so]       = *reinterpret_cast<uint32_t*>(&p0);
                    stgz[(rl0 + 8) * 68 + so] = *reinterpret_cast<uint32_t*>(&p1);
                }
            __syncthreads();   // (2)
            const uint4* sg4 = (const uint4*)(smem + OFF_STG);
            #pragma unroll
            for (int i = 0; i < 8; i++) {
                int e = tid + i * 256;       // 2048 uint4 = 128 rows x 16
                int r = e >> 4, c = e & 15;
                if (row0 + r < NV)
                    g_Zch4[(size_t)(row0 + r) * 48 + h * 16 + c] = sg4[r * 17 + c];
            }
            if (tid < 128 && row0 + tid < NV)
                g_ec[h * NV + row0 + tid] = s_part[tid] + s_part[128 + tid];
        } else {
            // ---- int8 quant: row max -> stage (pitch 144B, conflict-free) ----
            float mx[2][2];
            #pragma unroll
            for (int i = 0; i < 2; i++) {
                mx[i][0] = 0.f; mx[i][1] = 0.f;
                #pragma unroll
                for (int j = 0; j < 8; j++) {
                    mx[i][0] = fmaxf(mx[i][0], fmaxf(fabsf(acc[i][j][0]), fabsf(acc[i][j][1])));
                    mx[i][1] = fmaxf(mx[i][1], fmaxf(fabsf(acc[i][j][2]), fabsf(acc[i][j][3])));
                }
            }
            #pragma unroll
            for (int d = 1; d <= 2; d <<= 1)
                #pragma unroll
                for (int i = 0; i < 2; i++) {
                    mx[i][0] = fmaxf(mx[i][0], __shfl_xor_sync(0xFFFFFFFFu, mx[i][0], d));
                    mx[i][1] = fmaxf(mx[i][1], __shfl_xor_sync(0xFFFFFFFFu, mx[i][1], d));
                }
            if (tg == 0) {
                #pragma unroll
                for (int i = 0; i < 2; i++) {
                    s_rmx[wc * 128 + wr * 32 + i * 16 + g]     = mx[i][0];
                    s_rmx[wc * 128 + wr * 32 + i * 16 + 8 + g] = mx[i][1];
                }
            }
            __syncthreads();   // (1.5) row maxes visible

            uint8_t* stg = (uint8_t*)(smem + OFF_STG);
            #pragma unroll
            for (int i = 0; i < 2; i++)
                #pragma unroll
                for (int half = 0; half < 2; half++) {
                    int rl = wr * 32 + i * 16 + half * 8 + g;
                    float m = fmaxf(fmaxf(s_rmx[rl], s_rmx[128 + rl]), 1e-20f);
                    float inv = 127.0f / m;
                    #pragma unroll
                    for (int j = 0; j < 8; j++) {
                        int cc = wc * 64 + j * 8 + 2 * tg;
                        int q0 = __float2int_rn(acc[i][j][2 * half]     * inv) + 128;
                        int q1 = __float2int_rn(acc[i][j][2 * half + 1] * inv) + 128;
                        stg[rl * 144 + cc]     = (uint8_t)q0;
                        stg[rl * 144 + cc + 1] = (uint8_t)q1;
                    }
                }
            __syncthreads();   // (2)

            uint4* T = (gg < 6) ? g_V8i4 : g_V8n4;
            #pragma unroll
            for (int i = 0; i < 4; i++) {
                int e = tid + i * 256;       // 1024 uint4 = 128 rows x 8
                int r = e >> 3, q4 = e & 7;
                if (row0 + r < NV)
                    T[(size_t)(row0 + r) * 24 + h * 8 + q4] =
                        *(const uint4*)(stg + r * 144 + q4 * 16);
            }
            if (tid < 128 && row0 + tid < NV) {
                float s  = s_part[tid] + s_part[128 + tid];
                float sc = fmaxf(fmaxf(s_rmx[tid], s_rmx[128 + tid]), 1e-20f)
                           * (1.0f / 127.0f);
                float2* sdst = (gg < 6) ? g_si2 : g_sn2;
                sdst[h * NV + row0 + tid] = make_float2(s, sc);
            }
        }
    }
}

// =======================================================================
// Kernel 2: 4 vertices / 192-thread block; int8 gather with prmt unpack.
// =======================================================================
__global__ void __launch_bounds__(192) gather_kernel(
    const int*   __restrict__ nh_idx,
    const int*   __restrict__ int_idx,
    const float* __restrict__ nh_edges,
    const float* __restrict__ int_edges,
    float*       __restrict__ out)
{
    const int t  = threadIdx.x;
    const int nb = blockIdx.x * 4;

    __shared__ int      s_raw [4][2][MM];
    __shared__ uint32_t s_voff[4][2][MM];
    __shared__ float    s_alpha[4][6][MM];   // alpha * scale * 0.1

    if (t < 80) {
        int v = t / 20, r = t % 20;
        int br = r / 10, m = r % 10;
        int idx = (br ? nh_idx : int_idx)[(nb + v) * MM + m];
        s_raw[v][br][m]  = idx;
        s_voff[v][br][m] = (uint32_t)idx * 384u;
    }
    __syncthreads();

    #pragma unroll
    for (int rr = 0; rr < 2; rr++) {
        int gid  = (t >> 4) + rr * 12;
        int lane = t & 15;
        int v = gid / 6, grp = gid % 6;
        int br = grp / 3, h = grp % 3;
        int n = nb + v;
        float e = -1e30f, sc = 0.f;
        if (lane < MM) {
            int idx = s_raw[v][br][lane];
            float2 ssc = br ? g_sn2[h * NV + idx] : g_si2[h * NV + idx];
            float ed = (br ? nh_edges : int_edges)[n * MM + lane];
            e  = (ssc.x + g_ec[h * NV + n]) * ed;
            sc = ssc.y;
        }
        float mx = e;
        #pragma unroll
        for (int d = 8; d >= 1; d >>= 1)
            mx = fmaxf(mx, __shfl_xor_sync(0xFFFFFFFFu, mx, d, 16));
        float p = expf(e - mx);
        float sum = p;
        #pragma unroll
        for (int d = 8; d >= 1; d >>= 1)
            sum += __shfl_xor_sync(0xFFFFFFFFu, sum, d, 16);
        if (lane < MM)
            s_alpha[v][grp][lane] = p * (0.1f / sum) * sc;   // norm=10 folded
    }
    __syncthreads();

    const int v = t / 48;
    const int q = t % 48;
    const int n = nb + v;
    const int h = q >> 4;

    uint4 zp = g_Zch4[(size_t)n * 48 + q];
    const __half2* zh = (const __half2*)&zp;
    float2 z0 = __half22float2(zh[0]);
    float2 z1 = __half22float2(zh[1]);
    float2 z2 = __half22float2(zh[2]);
    float2 z3 = __half22float2(zh[3]);

    float acc[8];
    acc[0] = z0.x; acc[1] = z0.y; acc[2] = z1.x; acc[3] = z1.y;
    acc[4] = z2.x; acc[5] = z2.y; acc[6] = z3.x; acc[7] = z3.y;

    const char* Vi = (const char*)g_V8i4;
    const char* Vn = (const char*)g_V8n4;
    const uint32_t qoff = (uint32_t)q * 8u;

    #pragma unroll
    for (int m = 0; m < MM; m++) {
        float als = s_alpha[v][h][m];
        uint2 pv = *(const uint2*)(Vi + s_voff[v][0][m] + qoff);
        UNPACK_ACC(pv.x, 0x7440, als, acc[0]);
        UNPACK_ACC(pv.x, 0x7441, als, acc[1]);
        UNPACK_ACC(pv.x, 0x7442, als, acc[2]);
        UNPACK_ACC(pv.x, 0x7443, als, acc[3]);
        UNPACK_ACC(pv.y, 0x7440, als, acc[4]);
        UNPACK_ACC(pv.y, 0x7441, als, acc[5]);
        UNPACK_ACC(pv.y, 0x7442, als, acc[6]);
        UNPACK_ACC(pv.y, 0x7443, als, acc[7]);
    }
    #pragma unroll
    for (int m = 0; m < MM; m++) {
        float als = s_alpha[v][3 + h][m];
        uint2 pv = *(const uint2*)(Vn + s_voff[v][1][m] + qoff);
        UNPACK_ACC(pv.x, 0x7440, als, acc[0]);
        UNPACK_ACC(pv.x, 0x7441, als, acc[1]);
        UNPACK_ACC(pv.x, 0x7442, als, acc[2]);
        UNPACK_ACC(pv.x, 0x7443, als, acc[3]);
        UNPACK_ACC(pv.y, 0x7440, als, acc[4]);
        UNPACK_ACC(pv.y, 0x7441, als, acc[5]);
        UNPACK_ACC(pv.y, 0x7442, als, acc[6]);
        UNPACK_ACC(pv.y, 0x7443, als, acc[7]);
    }

    float4 o0, o1;
    o0.x = fmaxf(acc[0], 0.f); o0.y = fmaxf(acc[1], 0.f);
    o0.z = fmaxf(acc[2], 0.f); o0.w = fmaxf(acc[3], 0.f);
    o1.x = fmaxf(acc[4], 0.f); o1.y = fmaxf(acc[5], 0.f);
    o1.z = fmaxf(acc[6], 0.f); o1.w = fmaxf(acc[7], 0.f);
    float4* out4 = (float4*)out;
    out4[(size_t)n * 96 + 2 * q]     = o0;
    out4[(size_t)n * 96 + 2 * q + 1] = o1;
}

// -----------------------------------------------------------------------
extern "C" void kernel_launch(void* const* d_in, const int* in_sizes, int n_in,
                              void* d_out, int out_size)
{
    const float* vertices    = (const float*)d_in[0];
    const int*   nh_indices  = (const int*)  d_in[1];
    const int*   int_indices = (const int*)  d_in[2];
    const float* nh_edges    = (const float*)d_in[3];
    const float* int_edges   = (const float*)d_in[4];
    // d_in[5] = is_int: unused by the reference
    const float* Wvc         = (const float*)d_in[6];
    const float* bv          = (const float*)d_in[7];
    const float* Wvn_int     = (const float*)d_in[8];
    const float* Wvn_nh      = (const float*)d_in[9];
    const float* a           = (const float*)d_in[10];
    float* out = (float*)d_out;

    cudaFuncSetAttribute(prep_kernel, cudaFuncAttributeMaxDynamicSharedMemorySize, SMEM1_TOTAL);
    dim3 wgrid(9, 4);
    wprep_kernel<<<wgrid, 256>>>(Wvc, Wvn_int, Wvn_nh);
    prep_kernel<<<(NV + 127) / 128, 256, SMEM1_TOTAL>>>(vertices, a, bv);
    gather_kernel<<<NV / 4, 192>>>(nh_indices, int_indices, nh_edges, int_edges, out);
}

// round 7
// speedup vs baseline: 3.7239x; 1.1193x over previous
#include <cuda_runtime.h>
#include <cuda_fp16.h>
#include <cstdint>

#define NV 50000
#define HH 3
#define MM 10
#define APITCH 68            // u32 pitch (272B rows): conflict-free ldmatrix
#define TILE_B 34816         // 128 * 272 bytes per fp16 tile

// ---------------- device scratch (allocation-free rule) ----------------
__device__ uint4    g_Zch4 [(size_t)NV * 48];    // Zc (+bv) fp16 [n][384]
__device__ uint4    g_V8i4 [(size_t)NV * 24];    // Vint int8 [n][h*128+k]
__device__ uint4    g_V8n4 [(size_t)NV * 24];    // Vnh  int8
__device__ float2   g_si2  [HH * NV];            // {Vint.a_n, int8 scale} [h][n]
__device__ float2   g_sn2  [HH * NV];            // {Vnh.a_n,  int8 scale}
__device__ float    g_ec   [HH * NV];            // Zc . a_c
__device__ uint32_t g_Wt   [9 * 128 * APITCH];   // pre-transposed W, fp16 pairs

// ---------------- helpers ----------------
__device__ __forceinline__ uint32_t smem_u32(const void* p) {
    uint32_t a;
    asm("{ .reg .u64 t; cvta.to.shared.u64 t, %1; cvt.u32.u64 %0, t; }" : "=r"(a) : "l"(p));
    return a;
}
__device__ __forceinline__ void mma16816(float c[4], const uint32_t a[4],
                                         uint32_t b0, uint32_t b1) {
    asm volatile(
        "mma.sync.aligned.m16n8k16.row.col.f32.f16.f16.f32 "
        "{%0,%1,%2,%3}, {%4,%5,%6,%7}, {%8,%9}, {%0,%1,%2,%3};"
        : "+f"(c[0]), "+f"(c[1]), "+f"(c[2]), "+f"(c[3])
        : "r"(a[0]), "r"(a[1]), "r"(a[2]), "r"(a[3]), "r"(b0), "r"(b1));
}
#define LDM4(r, addr) \
    asm volatile("ldmatrix.sync.aligned.m8n8.x4.shared.b16 {%0,%1,%2,%3}, [%4];" \
        : "=r"((r)[0]), "=r"((r)[1]), "=r"((r)[2]), "=r"((r)[3]) : "r"(addr))

__device__ __forceinline__ uint32_t packh2(float a, float b) {
    __half2 h = __float22half2_rn(make_float2(a, b));
    return *reinterpret_cast<uint32_t*>(&h);
}

// byte of 'src' (biased-128 uint8) -> exact float q in [-127,127], fma with als
#define UNPACK_ACC(src, selimm, als, accv) do { \
    uint32_t _r; \
    asm("prmt.b32 %0, %1, %2, %3;" : "=r"(_r) : "r"(src), "r"(0x4B000000u), "n"(selimm)); \
    accv = fmaf(__uint_as_float(_r) - 8388736.0f, als, accv); \
} while (0)

// =======================================================================
// Kernel 0: transpose weights to fp16 pairs. grid (9,4), smem-tiled.
// =======================================================================
__global__ void wprep_kernel(const float* __restrict__ Wvc,
                             const float* __restrict__ Wint,
                             const float* __restrict__ Wnh)
{
    __shared__ float ws[128][33];
    const int g  = blockIdx.x;
    const int n0 = blockIdx.y * 32;
    const float* W = (g < 3) ? (Wvc  + (size_t)g       * 16384)
                   : (g < 6) ? (Wint + (size_t)(g - 3) * 16384)
                             : (Wnh  + (size_t)(g - 6) * 16384);
    const int tid = threadIdx.x;
    #pragma unroll
    for (int i = 0; i < 16; i++) {
        int idx = tid + i * 256;
        int f = idx >> 5, j = idx & 31;
        ws[f][j] = W[f * 128 + n0 + j];
    }
    __syncthreads();
    #pragma unroll
    for (int i = 0; i < 8; i++) {
        int idx = tid + i * 256;
        int nl = idx >> 6, f2 = idx & 63;
        g_Wt[g * 128 * APITCH + (n0 + nl) * APITCH + f2] =
            packh2(ws[2 * f2][nl], ws[2 * f2 + 1][nl]);
    }
}

// smem offsets (bytes): A | B0 | B1 | stage | scalars
#define OFF_A   0
#define OFF_B0  TILE_B
#define OFF_B1  (2 * TILE_B)
#define OFF_STG (3 * TILE_B)
#define OFF_AV  (4 * TILE_B)
#define OFF_BV  (4 * TILE_B + 512)
#define OFF_SP  (4 * TILE_B + 1024)
#define OFF_RMX (4 * TILE_B + 2048)
#define SMEM1_TOTAL (4 * TILE_B + 3072)      // 142336 B

__device__ __forceinline__ void copy_tile_async(uint32_t dst, const uint32_t* src) {
    for (int i = threadIdx.x; i < 2176; i += 256)
        asm volatile("cp.async.cg.shared.global [%0], [%1], 16;"
                     :: "r"(dst + i * 16), "l"(src + i * 4) : "memory");
}

// =======================================================================
// Kernel 1: 9x (X@W) single-pass fp16 HMMA GEMM, double-buffered B.
//   gg 0-2 (Zc): -> fp16 (+bv) table + e_center
//   gg 3-8 (V):  -> int8 table + {s, scale} float2 table
// =======================================================================
__global__ void __launch_bounds__(256, 1) prep_kernel(
    const float* __restrict__ X,
    const float* __restrict__ a,
    const float* __restrict__ bv)
{
    extern __shared__ char smem[];
    const uint32_t sb = smem_u32(smem);
    float* sm_av  = (float*)(smem + OFF_AV);
    float* sm_bv  = (float*)(smem + OFF_BV);
    float* s_part = (float*)(smem + OFF_SP);
    float* s_rmx  = (float*)(smem + OFF_RMX);

    const int tid  = threadIdx.x;
    const int lane = tid & 31;
    const int wid  = tid >> 5;
    const int wr   = wid >> 1;
    const int wc   = wid & 1;
    const int g    = lane >> 2;
    const int tg   = lane & 3;
    const int row0 = blockIdx.x * 128;

    const uint32_t a_off = (uint32_t)((wr * 32 + (lane & 15)) * 272 + ((lane >> 4) << 4));
    const int t4 = lane >> 3;
    const uint32_t b_off = (uint32_t)((wc * 64 + ((t4 >> 1) << 3) + (lane & 7)) * 272
                                      + ((t4 & 1) << 4));

    // kick off B(0)
    copy_tile_async(sb + OFF_B0, g_Wt);
    asm volatile("cp.async.commit_group;" ::: "memory");

    // ---- load A (X tile 128x128) as fp16 pairs ----
    uint32_t* As = (uint32_t*)(smem + OFF_A);
    #pragma unroll
    for (int i = 0; i < 16; i++) {
        int fid = tid + i * 256;
        int r = fid >> 5;
        int c = (fid & 31) << 2;
        float4 v = make_float4(0.f, 0.f, 0.f, 0.f);
        if (row0 + r < NV) v = *(const float4*)(X + (size_t)(row0 + r) * 128 + c);
        int o = r * APITCH + (c >> 1);
        As[o]     = packh2(v.x, v.y);
        As[o + 1] = packh2(v.z, v.w);
    }

    for (int gg = 0; gg < 9; gg++) {
        const int h = gg % 3;
        const bool isZc = (gg < 3);

        if (tid < 128) {
            sm_av[tid] = a[h * 256 + (isZc ? 128 : 0) + tid];
            if (isZc) sm_bv[tid] = bv[h * 128 + tid];
        }
        // prefetch B(gg+1) into other buffer; wait for B(gg)
        if (gg < 8) {
            copy_tile_async(sb + (((gg + 1) & 1) ? OFF_B1 : OFF_B0),
                            g_Wt + (size_t)(gg + 1) * 128 * APITCH);
            asm volatile("cp.async.commit_group;" ::: "memory");
            asm volatile("cp.async.wait_group 1;" ::: "memory");
        } else {
            asm volatile("cp.async.wait_group 0;" ::: "memory");
        }
        __syncthreads();   // (b) B(gg)+av ready; stage consumed by prior copy-out

        const uint32_t Bb = sb + ((gg & 1) ? OFF_B1 : OFF_B0);

        float acc[2][8][4];
        #pragma unroll
        for (int i = 0; i < 2; i++)
            #pragma unroll
            for (int j = 0; j < 8; j++)
                #pragma unroll
                for (int q = 0; q < 4; q++) acc[i][j][q] = 0.f;

        #pragma unroll
        for (int ks = 0; ks < 8; ks++) {
            const uint32_t kb = ks * 32;
            uint32_t a0[4], a1[4], bb[4][4];
            LDM4(a0, sb + OFF_A + a_off + kb);
            LDM4(a1, sb + OFF_A + a_off + 4352 + kb);
            #pragma unroll
            for (int jj = 0; jj < 4; jj++)
                LDM4(bb[jj], Bb + b_off + jj * 4352 + kb);
            #pragma unroll
            for (int j = 0; j < 8; j++) {
                uint32_t b0 = bb[j >> 1][(j & 1) * 2];
                uint32_t b1 = bb[j >> 1][(j & 1) * 2 + 1];
                mma16816(acc[0][j], a0, b0, b1);
                mma16816(acc[1][j], a1, b0, b1);
            }
        }

        // ---- s-dot with av ----
        float sp[4] = {0.f, 0.f, 0.f, 0.f};
        #pragma unroll
        for (int i = 0; i < 2; i++)
            #pragma unroll
            for (int j = 0; j < 8; j++) {
                int col = wc * 64 + j * 8 + 2 * tg;
                float a0 = sm_av[col], a1 = sm_av[col + 1];
                sp[i * 2 + 0] += acc[i][j][0] * a0 + acc[i][j][1] * a1;
                sp[i * 2 + 1] += acc[i][j][2] * a0 + acc[i][j][3] * a1;
            }
        #pragma unroll
        for (int d = 1; d <= 2; d <<= 1)
            #pragma unroll
            for (int q = 0; q < 4; q++)
                sp[q] += __shfl_xor_sync(0xFFFFFFFFu, sp[q], d);
        if (tg == 0) {
            #pragma unroll
            for (int i = 0; i < 2; i++)
                #pragma unroll
                for (int half = 0; half < 2; half++)
                    s_part[wc * 128 + wr * 32 + i * 16 + half * 8 + g] = sp[i * 2 + half];
        }

        if (isZc) {
            // ---- fp16 (+bv) -> stage (pitch 68 u32, conflict-free) ----
            uint32_t* stgz = (uint32_t*)(smem + OFF_STG);
            #pragma unroll
            for (int i = 0; i < 2; i++)
                #pragma unroll
                for (int j = 0; j < 8; j++) {
                    int col = wc * 64 + j * 8 + 2 * tg;
                    float b0 = sm_bv[col], b1 = sm_bv[col + 1];
                    int rl0 = wr * 32 + i * 16 + g;
                    int so = wc * 32 + j * 4 + tg;
                    stgz[rl0 * 68 + so]       = packh2(acc[i][j][0] + b0, acc[i][j][1] + b1);
                    stgz[(rl0 + 8) * 68 + so] = packh2(acc[i][j][2] + b0, acc[i][j][3] + b1);
                }
            __syncthreads();   // (2)
            const uint4* sg4 = (const uint4*)(smem + OFF_STG);
            #pragma unroll
            for (int i = 0; i < 8; i++) {
                int e = tid + i * 256;
                int r = e >> 4, c = e & 15;
                if (row0 + r < NV)
                    g_Zch4[(size_t)(row0 + r) * 48 + h * 16 + c] = sg4[r * 17 + c];
            }
            if (tid < 128 && row0 + tid < NV)
                g_ec[h * NV + row0 + tid] = s_part[tid] + s_part[128 + tid];
        } else {
            // ---- int8 quant: row max -> stage (pitch 144B, conflict-free) ----
            float mx[2][2];
            #pragma unroll
            for (int i = 0; i < 2; i++) {
                mx[i][0] = 0.f; mx[i][1] = 0.f;
                #pragma unroll
                for (int j = 0; j < 8; j++) {
                    mx[i][0] = fmaxf(mx[i][0], fmaxf(fabsf(acc[i][j][0]), fabsf(acc[i][j][1])));
                    mx[i][1] = fmaxf(mx[i][1], fmaxf(fabsf(acc[i][j][2]), fabsf(acc[i][j][3])));
                }
            }
            #pragma unroll
            for (int d = 1; d <= 2; d <<= 1)
                #pragma unroll
                for (int i = 0; i < 2; i++) {
                    mx[i][0] = fmaxf(mx[i][0], __shfl_xor_sync(0xFFFFFFFFu, mx[i][0], d));
                    mx[i][1] = fmaxf(mx[i][1], __shfl_xor_sync(0xFFFFFFFFu, mx[i][1], d));
                }
            if (tg == 0) {
                #pragma unroll
                for (int i = 0; i < 2; i++) {
                    s_rmx[wc * 128 + wr * 32 + i * 16 + g]     = mx[i][0];
                    s_rmx[wc * 128 + wr * 32 + i * 16 + 8 + g] = mx[i][1];
                }
            }
            __syncthreads();   // (1.5) row maxes visible

            uint8_t* stg = (uint8_t*)(smem + OFF_STG);
            #pragma unroll
            for (int i = 0; i < 2; i++)
                #pragma unroll
                for (int half = 0; half < 2; half++) {
                    int rl = wr * 32 + i * 16 + half * 8 + g;
                    float m = fmaxf(fmaxf(s_rmx[rl], s_rmx[128 + rl]), 1e-20f);
                    float inv = 127.0f / m;
                    #pragma unroll
                    for (int j = 0; j < 8; j++) {
                        int cc = wc * 64 + j * 8 + 2 * tg;
                        int q0 = __float2int_rn(acc[i][j][2 * half]     * inv) + 128;
                        int q1 = __float2int_rn(acc[i][j][2 * half + 1] * inv) + 128;
                        stg[rl * 144 + cc]     = (uint8_t)q0;
                        stg[rl * 144 + cc + 1] = (uint8_t)q1;
                    }
                }
            __syncthreads();   // (2)

            uint4* T = (gg < 6) ? g_V8i4 : g_V8n4;
            #pragma unroll
            for (int i = 0; i < 4; i++) {
                int e = tid + i * 256;
                int r = e >> 3, q4 = e & 7;
                if (row0 + r < NV)
                    T[(size_t)(row0 + r) * 24 + h * 8 + q4] =
                        *(const uint4*)(stg + r * 144 + q4 * 16);
            }
            if (tid < 128 && row0 + tid < NV) {
                float s  = s_part[tid] + s_part[128 + tid];
                float sc = fmaxf(fmaxf(s_rmx[tid], s_rmx[128 + tid]), 1e-20f)
                           * (1.0f / 127.0f);
                float2* sdst = (gg < 6) ? g_si2 : g_sn2;
                sdst[h * NV + row0 + tid] = make_float2(s, sc);
            }
        }
    }
}

// =======================================================================
// Kernel 2: 8 vertices / 192-thread block; 24 threads/vertex, LDG.128 gathers.
// =======================================================================
__global__ void __launch_bounds__(192) gather_kernel(
    const int*   __restrict__ nh_idx,
    const int*   __restrict__ int_idx,
    const float* __restrict__ nh_edges,
    const float* __restrict__ int_edges,
    float*       __restrict__ out)
{
    const int t  = threadIdx.x;
    const int nb = blockIdx.x * 8;

    __shared__ int      s_raw [8][2][MM];
    __shared__ uint32_t s_voff[8][2][MM];
    __shared__ float    s_alpha[8][6][MM];   // alpha * scale * 0.1

    if (t < 160) {
        int v = t / 20, r = t % 20;
        int br = r / 10, m = r % 10;
        int idx = (br ? nh_idx : int_idx)[(nb + v) * MM + m];
        s_raw[v][br][m]  = idx;
        s_voff[v][br][m] = (uint32_t)idx * 384u;
    }
    __syncthreads();

    #pragma unroll
    for (int rr = 0; rr < 4; rr++) {
        int gid  = (t >> 4) + rr * 12;     // 0..47 = 8v x 6grp
        int lane = t & 15;
        int v = gid / 6, grp = gid % 6;
        int br = grp / 3, h = grp % 3;
        int n = nb + v;
        float e = -1e30f, sc = 0.f;
        if (lane < MM) {
            int idx = s_raw[v][br][lane];
            float2 ssc = br ? g_sn2[h * NV + idx] : g_si2[h * NV + idx];
            float ed = (br ? nh_edges : int_edges)[n * MM + lane];
            e  = (ssc.x + g_ec[h * NV + n]) * ed;
            sc = ssc.y;
        }
        float mx = e;
        #pragma unroll
        for (int d = 8; d >= 1; d >>= 1)
            mx = fmaxf(mx, __shfl_xor_sync(0xFFFFFFFFu, mx, d, 16));
        float p = expf(e - mx);
        float sum = p;
        #pragma unroll
        for (int d = 8; d >= 1; d >>= 1)
            sum += __shfl_xor_sync(0xFFFFFFFFu, sum, d, 16);
        if (lane < MM)
            s_alpha[v][grp][lane] = p * (0.1f / sum) * sc;   // norm=10 folded
    }
    __syncthreads();

    const int v = t / 24;
    const int q = t % 24;          // 16-byte slot (16 features)
    const int n = nb + v;
    const int h = q >> 3;

    float acc[16];
    {
        uint4 zp0 = g_Zch4[(size_t)n * 48 + 2 * q];
        uint4 zp1 = g_Zch4[(size_t)n * 48 + 2 * q + 1];
        const __half2* zh0 = (const __half2*)&zp0;
        const __half2* zh1 = (const __half2*)&zp1;
        #pragma unroll
        for (int i = 0; i < 4; i++) {
            float2 f0 = __half22float2(zh0[i]);
            float2 f1 = __half22float2(zh1[i]);
            acc[2 * i]     = f0.x; acc[2 * i + 1]     = f0.y;
            acc[8 + 2 * i] = f1.x; acc[8 + 2 * i + 1] = f1.y;
        }
    }

    const char* Vi = (const char*)g_V8i4;
    const char* Vn = (const char*)g_V8n4;
    const uint32_t qoff = (uint32_t)q * 16u;

    #pragma unroll
    for (int m = 0; m < MM; m++) {
        float als = s_alpha[v][h][m];
        uint4 pv = *(const uint4*)(Vi + s_voff[v][0][m] + qoff);
        UNPACK_ACC(pv.x, 0x7440, als, acc[0]);
        UNPACK_ACC(pv.x, 0x7441, als, acc[1]);
        UNPACK_ACC(pv.x, 0x7442, als, acc[2]);
        UNPACK_ACC(pv.x, 0x7443, als, acc[3]);
        UNPACK_ACC(pv.y, 0x7440, als, acc[4]);
        UNPACK_ACC(pv.y, 0x7441, als, acc[5]);
        UNPACK_ACC(pv.y, 0x7442, als, acc[6]);
        UNPACK_ACC(pv.y, 0x7443, als, acc[7]);
        UNPACK_ACC(pv.z, 0x7440, als, acc[8]);
        UNPACK_ACC(pv.z, 0x7441, als, acc[9]);
        UNPACK_ACC(pv.z, 0x7442, als, acc[10]);
        UNPACK_ACC(pv.z, 0x7443, als, acc[11]);
        UNPACK_ACC(pv.w, 0x7440, als, acc[12]);
        UNPACK_ACC(pv.w, 0x7441, als, acc[13]);
        UNPACK_ACC(pv.w, 0x7442, als, acc[14]);
        UNPACK_ACC(pv.w, 0x7443, als, acc[15]);
    }
    #pragma unroll
    for (int m = 0; m < MM; m++) {
        float als = s_alpha[v][3 + h][m];
        uint4 pv = *(const uint4*)(Vn + s_voff[v][1][m] + qoff);
        UNPACK_ACC(pv.x, 0x7440, als, acc[0]);
        UNPACK_ACC(pv.x, 0x7441, als, acc[1]);
        UNPACK_ACC(pv.x, 0x7442, als, acc[2]);
        UNPACK_ACC(pv.x, 0x7443, als, acc[3]);
        UNPACK_ACC(pv.y, 0x7440, als, acc[4]);
        UNPACK_ACC(pv.y, 0x7441, als, acc[5]);
        UNPACK_ACC(pv.y, 0x7442, als, acc[6]);
        UNPACK_ACC(pv.y, 0x7443, als, acc[7]);
        UNPACK_ACC(pv.z, 0x7440, als, acc[8]);
        UNPACK_ACC(pv.z, 0x7441, als, acc[9]);
        UNPACK_ACC(pv.z, 0x7442, als, acc[10]);
        UNPACK_ACC(pv.z, 0x7443, als, acc[11]);
        UNPACK_ACC(pv.w, 0x7440, als, acc[12]);
        UNPACK_ACC(pv.w, 0x7441, als, acc[13]);
        UNPACK_ACC(pv.w, 0x7442, als, acc[14]);
        UNPACK_ACC(pv.w, 0x7443, als, acc[15]);
    }

    float4* out4 = (float4*)out;
    #pragma unroll
    for (int i = 0; i < 4; i++) {
        float4 o;
        o.x = fmaxf(acc[4 * i],     0.f);
        o.y = fmaxf(acc[4 * i + 1], 0.f);
        o.z = fmaxf(acc[4 * i + 2], 0.f);
        o.w = fmaxf(acc[4 * i + 3], 0.f);
        out4[(size_t)n * 96 + q * 4 + i] = o;
    }
}

// -----------------------------------------------------------------------
extern "C" void kernel_launch(void* const* d_in, const int* in_sizes, int n_in,
                              void* d_out, int out_size)
{
    const float* vertices    = (const float*)d_in[0];
    const int*   nh_indices  = (const int*)  d_in[1];
    const int*   int_indices = (const int*)  d_in[2];
    const float* nh_edges    = (const float*)d_in[3];
    const float* int_edges   = (const float*)d_in[4];
    // d_in[5] = is_int: unused by the reference
    const float* Wvc         = (const float*)d_in[6];
    const float* bv          = (const float*)d_in[7];
    const float* Wvn_int     = (const float*)d_in[8];
    const float* Wvn_nh      = (const float*)d_in[9];
    const float* a           = (const float*)d_in[10];
    float* out = (float*)d_out;

    cudaFuncSetAttribute(prep_kernel, cudaFuncAttributeMaxDynamicSharedMemorySize, SMEM1_TOTAL);
    dim3 wgrid(9, 4);
    wprep_kernel<<<wgrid, 256>>>(Wvc, Wvn_int, Wvn_nh);
    prep_kernel<<<(NV + 127) / 128, 256, SMEM1_TOTAL>>>(vertices, a, bv);
    gather_kernel<<<NV / 8, 192>>>(nh_indices, int_indices, nh_edges, int_edges, out);
}

// round 8
// speedup vs baseline: 4.1229x; 1.1071x over previous
#include <cuda_runtime.h>
#include <cuda_fp16.h>
#include <cstdint>

#define NV 50000
#define HH 3
#define MM 10
#define APITCH 68            // u32 pitch (272B rows): conflict-free ldmatrix
#define TILE_B 34816         // 128 * 272 bytes per fp16 tile

// ---------------- device scratch (allocation-free rule) ----------------
__device__ uint4    g_Zch4 [(size_t)NV * 48];    // Zc (+bv) fp16 [n][384]
__device__ uint4    g_V8i4 [(size_t)NV * 24];    // Vint int8 [n][h*128+k]
__device__ uint4    g_V8n4 [(size_t)NV * 24];    // Vnh  int8
__device__ float2   g_si2  [HH * NV];            // {Vint.a_n, int8 scale} [h][n]
__device__ float2   g_sn2  [HH * NV];            // {Vnh.a_n,  int8 scale}
__device__ float    g_ec   [HH * NV];            // Zc . a_c
__device__ uint32_t g_Wt   [9 * 128 * APITCH];   // pre-transposed W, fp16 pairs

// ---------------- helpers ----------------
__device__ __forceinline__ uint32_t smem_u32(const void* p) {
    uint32_t a;
    asm("{ .reg .u64 t; cvta.to.shared.u64 t, %1; cvt.u32.u64 %0, t; }" : "=r"(a) : "l"(p));
    return a;
}
__device__ __forceinline__ void mma16816(float c[4], const uint32_t a[4],
                                         uint32_t b0, uint32_t b1) {
    asm volatile(
        "mma.sync.aligned.m16n8k16.row.col.f32.f16.f16.f32 "
        "{%0,%1,%2,%3}, {%4,%5,%6,%7}, {%8,%9}, {%0,%1,%2,%3};"
        : "+f"(c[0]), "+f"(c[1]), "+f"(c[2]), "+f"(c[3])
        : "r"(a[0]), "r"(a[1]), "r"(a[2]), "r"(a[3]), "r"(b0), "r"(b1));
}
#define LDM4(r, addr) \
    asm volatile("ldmatrix.sync.aligned.m8n8.x4.shared.b16 {%0,%1,%2,%3}, [%4];" \
        : "=r"((r)[0]), "=r"((r)[1]), "=r"((r)[2]), "=r"((r)[3]) : "r"(addr))

__device__ __forceinline__ uint32_t packh2(float a, float b) {
    __half2 h = __float22half2_rn(make_float2(a, b));
    return *reinterpret_cast<uint32_t*>(&h);
}

// byte of 'src' (biased-128 uint8) -> exact float q in [-127,127], fma with als
#define UNPACK_ACC(src, selimm, als, accv) do { \
    uint32_t _r; \
    asm("prmt.b32 %0, %1, %2, %3;" : "=r"(_r) : "r"(src), "r"(0x4B000000u), "n"(selimm)); \
    accv = fmaf(__uint_as_float(_r) - 8388736.0f, als, accv); \
} while (0)

// =======================================================================
// Kernel 0: transpose weights to fp16 pairs. grid (9,4), smem-tiled.
// =======================================================================
__global__ void wprep_kernel(const float* __restrict__ Wvc,
                             const float* __restrict__ Wint,
                             const float* __restrict__ Wnh)
{
    __shared__ float ws[128][33];
    const int g  = blockIdx.x;
    const int n0 = blockIdx.y * 32;
    const float* W = (g < 3) ? (Wvc  + (size_t)g       * 16384)
                   : (g < 6) ? (Wint + (size_t)(g - 3) * 16384)
                             : (Wnh  + (size_t)(g - 6) * 16384);
    const int tid = threadIdx.x;
    #pragma unroll
    for (int i = 0; i < 16; i++) {
        int idx = tid + i * 256;
        int f = idx >> 5, j = idx & 31;
        ws[f][j] = W[f * 128 + n0 + j];
    }
    __syncthreads();
    #pragma unroll
    for (int i = 0; i < 8; i++) {
        int idx = tid + i * 256;
        int nl = idx >> 6, f2 = idx & 63;
        g_Wt[g * 128 * APITCH + (n0 + nl) * APITCH + f2] =
            packh2(ws[2 * f2][nl], ws[2 * f2 + 1][nl]);
    }
}

// smem offsets (bytes): A | B (single) | stage | scalars  -> 107520 B, 2 CTA/SM
#define OFF_A   0
#define OFF_B   TILE_B
#define OFF_STG (2 * TILE_B)
#define OFF_AV  (3 * TILE_B)
#define OFF_BV  (3 * TILE_B + 512)
#define OFF_SP  (3 * TILE_B + 1024)
#define OFF_RMX (3 * TILE_B + 2048)
#define SMEM1_TOTAL (3 * TILE_B + 3072)      // 107520 B

__device__ __forceinline__ void copy_tile_async(uint32_t dst, const uint32_t* src) {
    for (int i = threadIdx.x; i < 2176; i += 256)
        asm volatile("cp.async.cg.shared.global [%0], [%1], 16;"
                     :: "r"(dst + i * 16), "l"(src + i * 4) : "memory");
}

// =======================================================================
// Kernel 1: 9x (X@W) single-pass fp16 HMMA GEMM.
//   Single-buffered B: prefetch B(gg+1) post-MMA, overlapped with epilogue.
//   gg 0-2 (Zc): -> fp16 (+bv) table + e_center
//   gg 3-8 (V):  -> int8 table + {s, scale} float2 table
// =======================================================================
__global__ void __launch_bounds__(256, 2) prep_kernel(
    const float* __restrict__ X,
    const float* __restrict__ a,
    const float* __restrict__ bv)
{
    extern __shared__ char smem[];
    const uint32_t sb = smem_u32(smem);
    float* sm_av  = (float*)(smem + OFF_AV);
    float* sm_bv  = (float*)(smem + OFF_BV);
    float* s_part = (float*)(smem + OFF_SP);
    float* s_rmx  = (float*)(smem + OFF_RMX);

    const int tid  = threadIdx.x;
    const int lane = tid & 31;
    const int wid  = tid >> 5;
    const int wr   = wid >> 1;
    const int wc   = wid & 1;
    const int g    = lane >> 2;
    const int tg   = lane & 3;
    const int row0 = blockIdx.x * 128;

    const uint32_t a_off = (uint32_t)((wr * 32 + (lane & 15)) * 272 + ((lane >> 4) << 4));
    const int t4 = lane >> 3;
    const uint32_t b_off = (uint32_t)((wc * 64 + ((t4 >> 1) << 3) + (lane & 7)) * 272
                                      + ((t4 & 1) << 4));

    // kick off B(0)
    copy_tile_async(sb + OFF_B, g_Wt);
    asm volatile("cp.async.commit_group;" ::: "memory");

    // ---- load A (X tile 128x128) as fp16 pairs ----
    uint32_t* As = (uint32_t*)(smem + OFF_A);
    #pragma unroll
    for (int i = 0; i < 16; i++) {
        int fid = tid + i * 256;
        int r = fid >> 5;
        int c = (fid & 31) << 2;
        float4 v = make_float4(0.f, 0.f, 0.f, 0.f);
        if (row0 + r < NV) v = *(const float4*)(X + (size_t)(row0 + r) * 128 + c);
        int o = r * APITCH + (c >> 1);
        As[o]     = packh2(v.x, v.y);
        As[o + 1] = packh2(v.z, v.w);
    }

    for (int gg = 0; gg < 9; gg++) {
        const int h = gg % 3;
        const bool isZc = (gg < 3);

        if (tid < 128) {
            sm_av[tid] = a[h * 256 + (isZc ? 128 : 0) + tid];
            if (isZc) sm_bv[tid] = bv[h * 128 + tid];
        }
        asm volatile("cp.async.wait_group 0;" ::: "memory");
        __syncthreads();   // (b) B(gg)+av ready; stage consumed by prior copy-out

        float acc[2][8][4];
        #pragma unroll
        for (int i = 0; i < 2; i++)
            #pragma unroll
            for (int j = 0; j < 8; j++)
                #pragma unroll
                for (int q = 0; q < 4; q++) acc[i][j][q] = 0.f;

        #pragma unroll
        for (int ks = 0; ks < 8; ks++) {
            const uint32_t kb = ks * 32;
            uint32_t a0[4], a1[4], bb[4][4];
            LDM4(a0, sb + OFF_A + a_off + kb);
            LDM4(a1, sb + OFF_A + a_off + 4352 + kb);
            #pragma unroll
            for (int jj = 0; jj < 4; jj++)
                LDM4(bb[jj], sb + OFF_B + b_off + jj * 4352 + kb);
            #pragma unroll
            for (int j = 0; j < 8; j++) {
                uint32_t b0 = bb[j >> 1][(j & 1) * 2];
                uint32_t b1 = bb[j >> 1][(j & 1) * 2 + 1];
                mma16816(acc[0][j], a0, b0, b1);
                mma16816(acc[1][j], a1, b0, b1);
            }
        }
        __syncthreads();   // (1) all MMA reads of B done

        // prefetch B(gg+1) into the (single) B buffer; overlaps epilogue
        if (gg < 8) {
            copy_tile_async(sb + OFF_B, g_Wt + (size_t)(gg + 1) * 128 * APITCH);
            asm volatile("cp.async.commit_group;" ::: "memory");
        }

        // ---- s-dot with av ----
        float sp[4] = {0.f, 0.f, 0.f, 0.f};
        #pragma unroll
        for (int i = 0; i < 2; i++)
            #pragma unroll
            for (int j = 0; j < 8; j++) {
                int col = wc * 64 + j * 8 + 2 * tg;
                float a0 = sm_av[col], a1 = sm_av[col + 1];
                sp[i * 2 + 0] += acc[i][j][0] * a0 + acc[i][j][1] * a1;
                sp[i * 2 + 1] += acc[i][j][2] * a0 + acc[i][j][3] * a1;
            }
        #pragma unroll
        for (int d = 1; d <= 2; d <<= 1)
            #pragma unroll
            for (int q = 0; q < 4; q++)
                sp[q] += __shfl_xor_sync(0xFFFFFFFFu, sp[q], d);
        if (tg == 0) {
            #pragma unroll
            for (int i = 0; i < 2; i++)
                #pragma unroll
                for (int half = 0; half < 2; half++)
                    s_part[wc * 128 + wr * 32 + i * 16 + half * 8 + g] = sp[i * 2 + half];
        }

        if (isZc) {
            // ---- fp16 (+bv) -> stage (pitch 68 u32, conflict-free) ----
            uint32_t* stgz = (uint32_t*)(smem + OFF_STG);
            #pragma unroll
            for (int i = 0; i < 2; i++)
                #pragma unroll
                for (int j = 0; j < 8; j++) {
                    int col = wc * 64 + j * 8 + 2 * tg;
                    float b0 = sm_bv[col], b1 = sm_bv[col + 1];
                    int rl0 = wr * 32 + i * 16 + g;
                    int so = wc * 32 + j * 4 + tg;
                    stgz[rl0 * 68 + so]       = packh2(acc[i][j][0] + b0, acc[i][j][1] + b1);
                    stgz[(rl0 + 8) * 68 + so] = packh2(acc[i][j][2] + b0, acc[i][j][3] + b1);
                }
            __syncthreads();   // (2)
            const uint4* sg4 = (const uint4*)(smem + OFF_STG);
            #pragma unroll
            for (int i = 0; i < 8; i++) {
                int e = tid + i * 256;
                int r = e >> 4, c = e & 15;
                if (row0 + r < NV)
                    g_Zch4[(size_t)(row0 + r) * 48 + h * 16 + c] = sg4[r * 17 + c];
            }
            if (tid < 128 && row0 + tid < NV)
                g_ec[h * NV + row0 + tid] = s_part[tid] + s_part[128 + tid];
        } else {
            // ---- int8 quant: row max -> stage (pitch 144B, conflict-free) ----
            float mx[2][2];
            #pragma unroll
            for (int i = 0; i < 2; i++) {
                mx[i][0] = 0.f; mx[i][1] = 0.f;
                #pragma unroll
                for (int j = 0; j < 8; j++) {
                    mx[i][0] = fmaxf(mx[i][0], fmaxf(fabsf(acc[i][j][0]), fabsf(acc[i][j][1])));
                    mx[i][1] = fmaxf(mx[i][1], fmaxf(fabsf(acc[i][j][2]), fabsf(acc[i][j][3])));
                }
            }
            #pragma unroll
            for (int d = 1; d <= 2; d <<= 1)
                #pragma unroll
                for (int i = 0; i < 2; i++) {
                    mx[i][0] = fmaxf(mx[i][0], __shfl_xor_sync(0xFFFFFFFFu, mx[i][0], d));
                    mx[i][1] = fmaxf(mx[i][1], __shfl_xor_sync(0xFFFFFFFFu, mx[i][1], d));
                }
            if (tg == 0) {
                #pragma unroll
                for (int i = 0; i < 2; i++) {
                    s_rmx[wc * 128 + wr * 32 + i * 16 + g]     = mx[i][0];
                    s_rmx[wc * 128 + wr * 32 + i * 16 + 8 + g] = mx[i][1];
                }
            }
            __syncthreads();   // (1.5) row maxes visible

            uint8_t* stg = (uint8_t*)(smem + OFF_STG);
            #pragma unroll
            for (int i = 0; i < 2; i++)
                #pragma unroll
                for (int half = 0; half < 2; half++) {
                    int rl = wr * 32 + i * 16 + half * 8 + g;
                    float m = fmaxf(fmaxf(s_rmx[rl], s_rmx[128 + rl]), 1e-20f);
                    float inv = 127.0f / m;
                    #pragma unroll
                    for (int j = 0; j < 8; j++) {
                        int cc = wc * 64 + j * 8 + 2 * tg;
                        int q0 = __float2int_rn(acc[i][j][2 * half]     * inv) + 128;
                        int q1 = __float2int_rn(acc[i][j][2 * half + 1] * inv) + 128;
                        stg[rl * 144 + cc]     = (uint8_t)q0;
                        stg[rl * 144 + cc + 1] = (uint8_t)q1;
                    }
                }
            __syncthreads();   // (2)

            uint4* T = (gg < 6) ? g_V8i4 : g_V8n4;
            #pragma unroll
            for (int i = 0; i < 4; i++) {
                int e = tid + i * 256;
                int r = e >> 3, q4 = e & 7;
                if (row0 + r < NV)
                    T[(size_t)(row0 + r) * 24 + h * 8 + q4] =
                        *(const uint4*)(stg + r * 144 + q4 * 16);
            }
            if (tid < 128 && row0 + tid < NV) {
                float s  = s_part[tid] + s_part[128 + tid];
                float sc = fmaxf(fmaxf(s_rmx[tid], s_rmx[128 + tid]), 1e-20f)
                           * (1.0f / 127.0f);
                float2* sdst = (gg < 6) ? g_si2 : g_sn2;
                sdst[h * NV + row0 + tid] = make_float2(s, sc);
            }
        }
    }
}

// =======================================================================
// Kernel 2: 8 vertices / 192-thread block; 24 threads/vertex, LDG.128 gathers.
// =======================================================================
__global__ void __launch_bounds__(192) gather_kernel(
    const int*   __restrict__ nh_idx,
    const int*   __restrict__ int_idx,
    const float* __restrict__ nh_edges,
    const float* __restrict__ int_edges,
    float*       __restrict__ out)
{
    const int t  = threadIdx.x;
    const int nb = blockIdx.x * 8;

    __shared__ int      s_raw [8][2][MM];
    __shared__ uint32_t s_voff[8][2][MM];
    __shared__ float    s_alpha[8][6][MM];   // alpha * scale * 0.1

    if (t < 160) {
        int v = t / 20, r = t % 20;
        int br = r / 10, m = r % 10;
        int idx = (br ? nh_idx : int_idx)[(nb + v) * MM + m];
        s_raw[v][br][m]  = idx;
        s_voff[v][br][m] = (uint32_t)idx * 384u;
    }
    __syncthreads();

    #pragma unroll
    for (int rr = 0; rr < 4; rr++) {
        int gid  = (t >> 4) + rr * 12;     // 0..47 = 8v x 6grp
        int lane = t & 15;
        int v = gid / 6, grp = gid % 6;
        int br = grp / 3, h = grp % 3;
        int n = nb + v;
        float e = -1e30f, sc = 0.f;
        if (lane < MM) {
            int idx = s_raw[v][br][lane];
            float2 ssc = br ? g_sn2[h * NV + idx] : g_si2[h * NV + idx];
            float ed = (br ? nh_edges : int_edges)[n * MM + lane];
            e  = (ssc.x + g_ec[h * NV + n]) * ed;
            sc = ssc.y;
        }
        float mx = e;
        #pragma unroll
        for (int d = 8; d >= 1; d >>= 1)
            mx = fmaxf(mx, __shfl_xor_sync(0xFFFFFFFFu, mx, d, 16));
        float p = expf(e - mx);
        float sum = p;
        #pragma unroll
        for (int d = 8; d >= 1; d >>= 1)
            sum += __shfl_xor_sync(0xFFFFFFFFu, sum, d, 16);
        if (lane < MM)
            s_alpha[v][grp][lane] = p * (0.1f / sum) * sc;   // norm=10 folded
    }
    __syncthreads();

    const int v = t / 24;
    const int q = t % 24;          // 16-byte slot (16 features)
    const int n = nb + v;
    const int h = q >> 3;

    float acc[16];
    {
        uint4 zp0 = g_Zch4[(size_t)n * 48 + 2 * q];
        uint4 zp1 = g_Zch4[(size_t)n * 48 + 2 * q + 1];
        const __half2* zh0 = (const __half2*)&zp0;
        const __half2* zh1 = (const __half2*)&zp1;
        #pragma unroll
        for (int i = 0; i < 4; i++) {
            float2 f0 = __half22float2(zh0[i]);
            float2 f1 = __half22float2(zh1[i]);
            acc[2 * i]     = f0.x; acc[2 * i + 1]     = f0.y;
            acc[8 + 2 * i] = f1.x; acc[8 + 2 * i + 1] = f1.y;
        }
    }

    const char* Vi = (const char*)g_V8i4;
    const char* Vn = (const char*)g_V8n4;
    const uint32_t qoff = (uint32_t)q * 16u;

    #pragma unroll
    for (int m = 0; m < MM; m++) {
        float als = s_alpha[v][h][m];
        uint4 pv = *(const uint4*)(Vi + s_voff[v][0][m] + qoff);
        UNPACK_ACC(pv.x, 0x7440, als, acc[0]);
        UNPACK_ACC(pv.x, 0x7441, als, acc[1]);
        UNPACK_ACC(pv.x, 0x7442, als, acc[2]);
        UNPACK_ACC(pv.x, 0x7443, als, acc[3]);
        UNPACK_ACC(pv.y, 0x7440, als, acc[4]);
        UNPACK_ACC(pv.y, 0x7441, als, acc[5]);
        UNPACK_ACC(pv.y, 0x7442, als, acc[6]);
        UNPACK_ACC(pv.y, 0x7443, als, acc[7]);
        UNPACK_ACC(pv.z, 0x7440, als, acc[8]);
        UNPACK_ACC(pv.z, 0x7441, als, acc[9]);
        UNPACK_ACC(pv.z, 0x7442, als, acc[10]);
        UNPACK_ACC(pv.z, 0x7443, als, acc[11]);
        UNPACK_ACC(pv.w, 0x7440, als, acc[12]);
        UNPACK_ACC(pv.w, 0x7441, als, acc[13]);
        UNPACK_ACC(pv.w, 0x7442, als, acc[14]);
        UNPACK_ACC(pv.w, 0x7443, als, acc[15]);
    }
    #pragma unroll
    for (int m = 0; m < MM; m++) {
        float als = s_alpha[v][3 + h][m];
        uint4 pv = *(const uint4*)(Vn + s_voff[v][1][m] + qoff);
        UNPACK_ACC(pv.x, 0x7440, als, acc[0]);
        UNPACK_ACC(pv.x, 0x7441, als, acc[1]);
        UNPACK_ACC(pv.x, 0x7442, als, acc[2]);
        UNPACK_ACC(pv.x, 0x7443, als, acc[3]);
        UNPACK_ACC(pv.y, 0x7440, als, acc[4]);
        UNPACK_ACC(pv.y, 0x7441, als, acc[5]);
        UNPACK_ACC(pv.y, 0x7442, als, acc[6]);
        UNPACK_ACC(pv.y, 0x7443, als, acc[7]);
        UNPACK_ACC(pv.z, 0x7440, als, acc[8]);
        UNPACK_ACC(pv.z, 0x7441, als, acc[9]);
        UNPACK_ACC(pv.z, 0x7442, als, acc[10]);
        UNPACK_ACC(pv.z, 0x7443, als, acc[11]);
        UNPACK_ACC(pv.w, 0x7440, als, acc[12]);
        UNPACK_ACC(pv.w, 0x7441, als, acc[13]);
        UNPACK_ACC(pv.w, 0x7442, als, acc[14]);
        UNPACK_ACC(pv.w, 0x7443, als, acc[15]);
    }

    float4* out4 = (float4*)out;
    #pragma unroll
    for (int i = 0; i < 4; i++) {
        float4 o;
        o.x = fmaxf(acc[4 * i],     0.f);
        o.y = fmaxf(acc[4 * i + 1], 0.f);
        o.z = fmaxf(acc[4 * i + 2], 0.f);
        o.w = fmaxf(acc[4 * i + 3], 0.f);
        out4[(size_t)n * 96 + q * 4 + i] = o;
    }
}

// -----------------------------------------------------------------------
extern "C" void kernel_launch(void* const* d_in, const int* in_sizes, int n_in,
                              void* d_out, int out_size)
{
    const float* vertices    = (const float*)d_in[0];
    const int*   nh_indices  = (const int*)  d_in[1];
    const int*   int_indices = (const int*)  d_in[2];
    const float* nh_edges    = (const float*)d_in[3];
    const float* int_edges   = (const float*)d_in[4];
    // d_in[5] = is_int: unused by the reference
    const float* Wvc         = (const float*)d_in[6];
    const float* bv          = (const float*)d_in[7];
    const float* Wvn_int     = (const float*)d_in[8];
    const float* Wvn_nh      = (const float*)d_in[9];
    const float* a           = (const float*)d_in[10];
    float* out = (float*)d_out;

    cudaFuncSetAttribute(prep_kernel, cudaFuncAttributeMaxDynamicSharedMemorySize, SMEM1_TOTAL);
    dim3 wgrid(9, 4);
    wprep_kernel<<<wgrid, 256>>>(Wvc, Wvn_int, Wvn_nh);
    prep_kernel<<<(NV + 127) / 128, 256, SMEM1_TOTAL>>>(vertices, a, bv);
    gather_kernel<<<NV / 8, 192>>>(nh_indices, int_indices, nh_edges, int_edges, out);
}

// round 9
// speedup vs baseline: 4.1776x; 1.0133x over previous
#include <cuda_runtime.h>
#include <cuda_fp16.h>
#include <cstdint>

#define NV 50000
#define HH 3
#define MM 10
#define APITCH 68            // u32 pitch (272B rows): conflict-free ldmatrix
#define TILE_B 34816         // 128 * 272 bytes per fp16 tile

// ---------------- device scratch (allocation-free rule) ----------------
__device__ uint4    g_Zch4 [(size_t)NV * 48];    // Zc (+bv) fp16 [n][384]
__device__ uint4    g_V8i4 [(size_t)NV * 24];    // Vint int8 [n][h*128+k]
__device__ uint4    g_V8n4 [(size_t)NV * 24];    // Vnh  int8
__device__ float2   g_si2  [HH * NV];            // {Vint.a_n, int8 scale} [h][n]
__device__ float2   g_sn2  [HH * NV];            // {Vnh.a_n,  int8 scale}
__device__ float    g_ec   [HH * NV];            // Zc . a_c
__device__ uint32_t g_Wt   [9 * 128 * APITCH];   // pre-transposed W, fp16 pairs

// ---------------- helpers ----------------
__device__ __forceinline__ uint32_t smem_u32(const void* p) {
    uint32_t a;
    asm("{ .reg .u64 t; cvta.to.shared.u64 t, %1; cvt.u32.u64 %0, t; }" : "=r"(a) : "l"(p));
    return a;
}
__device__ __forceinline__ void mma16816(float c[4], const uint32_t a[4],
                                         uint32_t b0, uint32_t b1) {
    asm volatile(
        "mma.sync.aligned.m16n8k16.row.col.f32.f16.f16.f32 "
        "{%0,%1,%2,%3}, {%4,%5,%6,%7}, {%8,%9}, {%0,%1,%2,%3};"
        : "+f"(c[0]), "+f"(c[1]), "+f"(c[2]), "+f"(c[3])
        : "r"(a[0]), "r"(a[1]), "r"(a[2]), "r"(a[3]), "r"(b0), "r"(b1));
}
#define LDM4(r, addr) \
    asm volatile("ldmatrix.sync.aligned.m8n8.x4.shared.b16 {%0,%1,%2,%3}, [%4];" \
        : "=r"((r)[0]), "=r"((r)[1]), "=r"((r)[2]), "=r"((r)[3]) : "r"(addr))

__device__ __forceinline__ uint32_t packh2(float a, float b) {
    __half2 h = __float22half2_rn(make_float2(a, b));
    return *reinterpret_cast<uint32_t*>(&h);
}

// two bytes of 'src' (biased-128 uint8) -> packed f32x2 {q0,q1} exact, fma w/ als2
// magic: prmt builds 0x4B0000xx = float(2^23 + 128 + q); subtract 8388736 -> q
#define UNPACK2_ACC(src, sel0, sel1, als2, acc2, negmagic2) do { \
    uint32_t _lo, _hi; uint64_t _p; \
    asm("prmt.b32 %0, %1, %2, %3;" : "=r"(_lo) : "r"(src), "r"(0x4B000000u), "n"(sel0)); \
    asm("prmt.b32 %0, %1, %2, %3;" : "=r"(_hi) : "r"(src), "r"(0x4B000000u), "n"(sel1)); \
    asm("mov.b64 %0, {%1, %2};" : "=l"(_p) : "r"(_lo), "r"(_hi)); \
    asm("add.rn.f32x2 %0, %0, %1;" : "+l"(_p) : "l"(negmagic2)); \
    asm("fma.rn.f32x2 %0, %1, %2, %0;" : "+l"(acc2) : "l"(_p), "l"(als2)); \
} while (0)

// =======================================================================
// Kernel 0: transpose weights to fp16 pairs. grid (9,4), smem-tiled.
// =======================================================================
__global__ void wprep_kernel(const float* __restrict__ Wvc,
                             const float* __restrict__ Wint,
                             const float* __restrict__ Wnh)
{
    __shared__ float ws[128][33];
    const int g  = blockIdx.x;
    const int n0 = blockIdx.y * 32;
    const float* W = (g < 3) ? (Wvc  + (size_t)g       * 16384)
                   : (g < 6) ? (Wint + (size_t)(g - 3) * 16384)
                             : (Wnh  + (size_t)(g - 6) * 16384);
    const int tid = threadIdx.x;
    #pragma unroll
    for (int i = 0; i < 16; i++) {
        int idx = tid + i * 256;
        int f = idx >> 5, j = idx & 31;
        ws[f][j] = W[f * 128 + n0 + j];
    }
    __syncthreads();
    #pragma unroll
    for (int i = 0; i < 8; i++) {
        int idx = tid + i * 256;
        int nl = idx >> 6, f2 = idx & 63;
        g_Wt[g * 128 * APITCH + (n0 + nl) * APITCH + f2] =
            packh2(ws[2 * f2][nl], ws[2 * f2 + 1][nl]);
    }
}

// smem offsets (bytes): A | B (single) | stage | scalars  -> 107520 B, 2 CTA/SM
#define OFF_A   0
#define OFF_B   TILE_B
#define OFF_STG (2 * TILE_B)
#define OFF_AV  (3 * TILE_B)
#define OFF_BV  (3 * TILE_B + 512)
#define OFF_SP  (3 * TILE_B + 1024)
#define OFF_RMX (3 * TILE_B + 2048)
#define SMEM1_TOTAL (3 * TILE_B + 3072)      // 107520 B

__device__ __forceinline__ void copy_tile_async(uint32_t dst, const uint32_t* src) {
    for (int i = threadIdx.x; i < 2176; i += 256)
        asm volatile("cp.async.cg.shared.global [%0], [%1], 16;"
                     :: "r"(dst + i * 16), "l"(src + i * 4) : "memory");
}

// =======================================================================
// Kernel 1: 9x (X@W) single-pass fp16 HMMA GEMM.
//   Single-buffered B: prefetch B(gg+1) post-MMA, overlapped with epilogue.
//   gg 0-2 (Zc): -> fp16 (+bv) table + e_center
//   gg 3-8 (V):  -> int8 table + {s, scale} float2 table
// =======================================================================
__global__ void __launch_bounds__(256, 2) prep_kernel(
    const float* __restrict__ X,
    const float* __restrict__ a,
    const float* __restrict__ bv)
{
    extern __shared__ char smem[];
    const uint32_t sb = smem_u32(smem);
    float* sm_av  = (float*)(smem + OFF_AV);
    float* sm_bv  = (float*)(smem + OFF_BV);
    float* s_part = (float*)(smem + OFF_SP);
    float* s_rmx  = (float*)(smem + OFF_RMX);

    const int tid  = threadIdx.x;
    const int lane = tid & 31;
    const int wid  = tid >> 5;
    const int wr   = wid >> 1;
    const int wc   = wid & 1;
    const int g    = lane >> 2;
    const int tg   = lane & 3;
    const int row0 = blockIdx.x * 128;

    const uint32_t a_off = (uint32_t)((wr * 32 + (lane & 15)) * 272 + ((lane >> 4) << 4));
    const int t4 = lane >> 3;
    const uint32_t b_off = (uint32_t)((wc * 64 + ((t4 >> 1) << 3) + (lane & 7)) * 272
                                      + ((t4 & 1) << 4));

    // kick off B(0)
    copy_tile_async(sb + OFF_B, g_Wt);
    asm volatile("cp.async.commit_group;" ::: "memory");

    // ---- load A (X tile 128x128) as fp16 pairs ----
    uint32_t* As = (uint32_t*)(smem + OFF_A);
    #pragma unroll
    for (int i = 0; i < 16; i++) {
        int fid = tid + i * 256;
        int r = fid >> 5;
        int c = (fid & 31) << 2;
        float4 v = make_float4(0.f, 0.f, 0.f, 0.f);
        if (row0 + r < NV) v = *(const float4*)(X + (size_t)(row0 + r) * 128 + c);
        int o = r * APITCH + (c >> 1);
        As[o]     = packh2(v.x, v.y);
        As[o + 1] = packh2(v.z, v.w);
    }

    for (int gg = 0; gg < 9; gg++) {
        const int h = gg % 3;
        const bool isZc = (gg < 3);

        if (tid < 128) {
            sm_av[tid] = a[h * 256 + (isZc ? 128 : 0) + tid];
            if (isZc) sm_bv[tid] = bv[h * 128 + tid];
        }
        asm volatile("cp.async.wait_group 0;" ::: "memory");
        __syncthreads();   // (b) B(gg)+av ready; stage consumed by prior copy-out

        float acc[2][8][4];
        #pragma unroll
        for (int i = 0; i < 2; i++)
            #pragma unroll
            for (int j = 0; j < 8; j++)
                #pragma unroll
                for (int q = 0; q < 4; q++) acc[i][j][q] = 0.f;

        #pragma unroll
        for (int ks = 0; ks < 8; ks++) {
            const uint32_t kb = ks * 32;
            uint32_t a0[4], a1[4], bb[4][4];
            LDM4(a0, sb + OFF_A + a_off + kb);
            LDM4(a1, sb + OFF_A + a_off + 4352 + kb);
            #pragma unroll
            for (int jj = 0; jj < 4; jj++)
                LDM4(bb[jj], sb + OFF_B + b_off + jj * 4352 + kb);
            #pragma unroll
            for (int j = 0; j < 8; j++) {
                uint32_t b0 = bb[j >> 1][(j & 1) * 2];
                uint32_t b1 = bb[j >> 1][(j & 1) * 2 + 1];
                mma16816(acc[0][j], a0, b0, b1);
                mma16816(acc[1][j], a1, b0, b1);
            }
        }
        __syncthreads();   // (1) all MMA reads of B done

        // prefetch B(gg+1) into the (single) B buffer; overlaps epilogue
        if (gg < 8) {
            copy_tile_async(sb + OFF_B, g_Wt + (size_t)(gg + 1) * 128 * APITCH);
            asm volatile("cp.async.commit_group;" ::: "memory");
        }

        // ---- s-dot with av ----
        float sp[4] = {0.f, 0.f, 0.f, 0.f};
        #pragma unroll
        for (int i = 0; i < 2; i++)
            #pragma unroll
            for (int j = 0; j < 8; j++) {
                int col = wc * 64 + j * 8 + 2 * tg;
                float a0 = sm_av[col], a1 = sm_av[col + 1];
                sp[i * 2 + 0] += acc[i][j][0] * a0 + acc[i][j][1] * a1;
                sp[i * 2 + 1] += acc[i][j][2] * a0 + acc[i][j][3] * a1;
            }
        #pragma unroll
        for (int d = 1; d <= 2; d <<= 1)
            #pragma unroll
            for (int q = 0; q < 4; q++)
                sp[q] += __shfl_xor_sync(0xFFFFFFFFu, sp[q], d);
        if (tg == 0) {
            #pragma unroll
            for (int i = 0; i < 2; i++)
                #pragma unroll
                for (int half = 0; half < 2; half++)
                    s_part[wc * 128 + wr * 32 + i * 16 + half * 8 + g] = sp[i * 2 + half];
        }

        if (isZc) {
            // ---- fp16 (+bv) -> stage (pitch 68 u32, conflict-free) ----
            uint32_t* stgz = (uint32_t*)(smem + OFF_STG);
            #pragma unroll
            for (int i = 0; i < 2; i++)
                #pragma unroll
                for (int j = 0; j < 8; j++) {
                    int col = wc * 64 + j * 8 + 2 * tg;
                    float b0 = sm_bv[col], b1 = sm_bv[col + 1];
                    int rl0 = wr * 32 + i * 16 + g;
                    int so = wc * 32 + j * 4 + tg;
                    stgz[rl0 * 68 + so]       = packh2(acc[i][j][0] + b0, acc[i][j][1] + b1);
                    stgz[(rl0 + 8) * 68 + so] = packh2(acc[i][j][2] + b0, acc[i][j][3] + b1);
                }
            __syncthreads();   // (2)
            const uint4* sg4 = (const uint4*)(smem + OFF_STG);
            #pragma unroll
            for (int i = 0; i < 8; i++) {
                int e = tid + i * 256;
                int r = e >> 4, c = e & 15;
                if (row0 + r < NV)
                    g_Zch4[(size_t)(row0 + r) * 48 + h * 16 + c] = sg4[r * 17 + c];
            }
            if (tid < 128 && row0 + tid < NV)
                g_ec[h * NV + row0 + tid] = s_part[tid] + s_part[128 + tid];
        } else {
            // ---- int8 quant: row max -> stage (pitch 144B, conflict-free) ----
            float mx[2][2];
            #pragma unroll
            for (int i = 0; i < 2; i++) {
                mx[i][0] = 0.f; mx[i][1] = 0.f;
                #pragma unroll
                for (int j = 0; j < 8; j++) {
                    mx[i][0] = fmaxf(mx[i][0], fmaxf(fabsf(acc[i][j][0]), fabsf(acc[i][j][1])));
                    mx[i][1] = fmaxf(mx[i][1], fmaxf(fabsf(acc[i][j][2]), fabsf(acc[i][j][3])));
                }
            }
            #pragma unroll
            for (int d = 1; d <= 2; d <<= 1)
                #pragma unroll
                for (int i = 0; i < 2; i++) {
                    mx[i][0] = fmaxf(mx[i][0], __shfl_xor_sync(0xFFFFFFFFu, mx[i][0], d));
                    mx[i][1] = fmaxf(mx[i][1], __shfl_xor_sync(0xFFFFFFFFu, mx[i][1], d));
                }
            if (tg == 0) {
                #pragma unroll
                for (int i = 0; i < 2; i++) {
                    s_rmx[wc * 128 + wr * 32 + i * 16 + g]     = mx[i][0];
                    s_rmx[wc * 128 + wr * 32 + i * 16 + 8 + g] = mx[i][1];
                }
            }
            __syncthreads();   // (1.5) row maxes visible

            uint8_t* stg = (uint8_t*)(smem + OFF_STG);
            #pragma unroll
            for (int i = 0; i < 2; i++)
                #pragma unroll
                for (int half = 0; half < 2; half++) {
                    int rl = wr * 32 + i * 16 + half * 8 + g;
                    float m = fmaxf(fmaxf(s_rmx[rl], s_rmx[128 + rl]), 1e-20f);
                    float inv = 127.0f / m;
                    #pragma unroll
                    for (int j = 0; j < 8; j++) {
                        int cc = wc * 64 + j * 8 + 2 * tg;
                        int q0 = __float2int_rn(acc[i][j][2 * half]     * inv) + 128;
                        int q1 = __float2int_rn(acc[i][j][2 * half + 1] * inv) + 128;
                        stg[rl * 144 + cc]     = (uint8_t)q0;
                        stg[rl * 144 + cc + 1] = (uint8_t)q1;
                    }
                }
            __syncthreads();   // (2)

            uint4* T = (gg < 6) ? g_V8i4 : g_V8n4;
            #pragma unroll
            for (int i = 0; i < 4; i++) {
                int e = tid + i * 256;
                int r = e >> 3, q4 = e & 7;
                if (row0 + r < NV)
                    T[(size_t)(row0 + r) * 24 + h * 8 + q4] =
                        *(const uint4*)(stg + r * 144 + q4 * 16);
            }
            if (tid < 128 && row0 + tid < NV) {
                float s  = s_part[tid] + s_part[128 + tid];
                float sc = fmaxf(fmaxf(s_rmx[tid], s_rmx[128 + tid]), 1e-20f)
                           * (1.0f / 127.0f);
                float2* sdst = (gg < 6) ? g_si2 : g_sn2;
                sdst[h * NV + row0 + tid] = make_float2(s, sc);
            }
        }
    }
}

// =======================================================================
// Kernel 2: 8 vertices / 192-thread block; 24 threads/vertex, LDG.128
// gathers, f32x2 packed unpack-accumulate.
// =======================================================================
__global__ void __launch_bounds__(192) gather_kernel(
    const int*   __restrict__ nh_idx,
    const int*   __restrict__ int_idx,
    const float* __restrict__ nh_edges,
    const float* __restrict__ int_edges,
    float*       __restrict__ out)
{
    const int t  = threadIdx.x;
    const int nb = blockIdx.x * 8;

    __shared__ int      s_raw [8][2][MM];
    __shared__ uint32_t s_voff[8][2][MM];
    __shared__ float    s_alpha[8][6][MM];   // alpha * scale * 0.1

    if (t < 160) {
        int v = t / 20, r = t % 20;
        int br = r / 10, m = r % 10;
        int idx = (br ? nh_idx : int_idx)[(nb + v) * MM + m];
        s_raw[v][br][m]  = idx;
        s_voff[v][br][m] = (uint32_t)idx * 384u;
    }
    __syncthreads();

    #pragma unroll
    for (int rr = 0; rr < 4; rr++) {
        int gid  = (t >> 4) + rr * 12;     // 0..47 = 8v x 6grp
        int lane = t & 15;
        int v = gid / 6, grp = gid % 6;
        int br = grp / 3, h = grp % 3;
        int n = nb + v;
        float e = -1e30f, sc = 0.f;
        if (lane < MM) {
            int idx = s_raw[v][br][lane];
            float2 ssc = br ? g_sn2[h * NV + idx] : g_si2[h * NV + idx];
            float ed = (br ? nh_edges : int_edges)[n * MM + lane];
            e  = (ssc.x + g_ec[h * NV + n]) * ed;
            sc = ssc.y;
        }
        float mx = e;
        #pragma unroll
        for (int d = 8; d >= 1; d >>= 1)
            mx = fmaxf(mx, __shfl_xor_sync(0xFFFFFFFFu, mx, d, 16));
        float p = expf(e - mx);
        float sum = p;
        #pragma unroll
        for (int d = 8; d >= 1; d >>= 1)
            sum += __shfl_xor_sync(0xFFFFFFFFu, sum, d, 16);
        if (lane < MM)
            s_alpha[v][grp][lane] = p * (0.1f / sum) * sc;   // norm=10 folded
    }
    __syncthreads();

    const int v = t / 24;
    const int q = t % 24;          // 16-byte slot (16 features)
    const int n = nb + v;
    const int h = q >> 3;

    const uint64_t negmagic2 = 0xCB000080CB000080ULL;   // {-8388736.f, -8388736.f}

    uint64_t acc2[8];
    {
        uint4 zp0 = g_Zch4[(size_t)n * 48 + 2 * q];
        uint4 zp1 = g_Zch4[(size_t)n * 48 + 2 * q + 1];
        const __half2* zh0 = (const __half2*)&zp0;
        const __half2* zh1 = (const __half2*)&zp1;
        #pragma unroll
        for (int i = 0; i < 4; i++) {
            float2 f0 = __half22float2(zh0[i]);
            float2 f1 = __half22float2(zh1[i]);
            asm("mov.b64 %0, {%1, %2};" : "=l"(acc2[i])
                : "r"(__float_as_uint(f0.x)), "r"(__float_as_uint(f0.y)));
            asm("mov.b64 %0, {%1, %2};" : "=l"(acc2[4 + i])
                : "r"(__float_as_uint(f1.x)), "r"(__float_as_uint(f1.y)));
        }
    }

    const char* Vi = (const char*)g_V8i4;
    const char* Vn = (const char*)g_V8n4;
    const uint32_t qoff = (uint32_t)q * 16u;

    #pragma unroll
    for (int m = 0; m < MM; m++) {
        float als = s_alpha[v][h][m];
        uint64_t als2;
        asm("mov.b64 %0, {%1, %1};" : "=l"(als2) : "r"(__float_as_uint(als)));
        uint4 pv = *(const uint4*)(Vi + s_voff[v][0][m] + qoff);
        UNPACK2_ACC(pv.x, 0x7440, 0x7441, als2, acc2[0], negmagic2);
        UNPACK2_ACC(pv.x, 0x7442, 0x7443, als2, acc2[1], negmagic2);
        UNPACK2_ACC(pv.y, 0x7440, 0x7441, als2, acc2[2], negmagic2);
        UNPACK2_ACC(pv.y, 0x7442, 0x7443, als2, acc2[3], negmagic2);
        UNPACK2_ACC(pv.z, 0x7440, 0x7441, als2, acc2[4], negmagic2);
        UNPACK2_ACC(pv.z, 0x7442, 0x7443, als2, acc2[5], negmagic2);
        UNPACK2_ACC(pv.w, 0x7440, 0x7441, als2, acc2[6], negmagic2);
        UNPACK2_ACC(pv.w, 0x7442, 0x7443, als2, acc2[7], negmagic2);
    }
    #pragma unroll
    for (int m = 0; m < MM; m++) {
        float als = s_alpha[v][3 + h][m];
        uint64_t als2;
        asm("mov.b64 %0, {%1, %1};" : "=l"(als2) : "r"(__float_as_uint(als)));
        uint4 pv = *(const uint4*)(Vn + s_voff[v][1][m] + qoff);
        UNPACK2_ACC(pv.x, 0x7440, 0x7441, als2, acc2[0], negmagic2);
        UNPACK2_ACC(pv.x, 0x7442, 0x7443, als2, acc2[1], negmagic2);
        UNPACK2_ACC(pv.y, 0x7440, 0x7441, als2, acc2[2], negmagic2);
        UNPACK2_ACC(pv.y, 0x7442, 0x7443, als2, acc2[3], negmagic2);
        UNPACK2_ACC(pv.z, 0x7440, 0x7441, als2, acc2[4], negmagic2);
        UNPACK2_ACC(pv.z, 0x7442, 0x7443, als2, acc2[5], negmagic2);
        UNPACK2_ACC(pv.w, 0x7440, 0x7441, als2, acc2[6], negmagic2);
        UNPACK2_ACC(pv.w, 0x7442, 0x7443, als2, acc2[7], negmagic2);
    }

    float4* out4 = (float4*)out;
    #pragma unroll
    for (int i = 0; i < 2; i++) {
        float4 o;
        uint32_t lo, hi;
        asm("mov.b64 {%0, %1}, %2;" : "=r"(lo), "=r"(hi) : "l"(acc2[2 * i]));
        o.x = fmaxf(__uint_as_float(lo), 0.f);
        o.y = fmaxf(__uint_as_float(hi), 0.f);
        asm("mov.b64 {%0, %1}, %2;" : "=r"(lo), "=r"(hi) : "l"(acc2[2 * i + 1]));
        o.z = fmaxf(__uint_as_float(lo), 0.f);
        o.w = fmaxf(__uint_as_float(hi), 0.f);
        out4[(size_t)n * 96 + q * 4 + i] = o;

        float4 o2;
        asm("mov.b64 {%0, %1}, %2;" : "=r"(lo), "=r"(hi) : "l"(acc2[4 + 2 * i]));
        o2.x = fmaxf(__uint_as_float(lo), 0.f);
        o2.y = fmaxf(__uint_as_float(hi), 0.f);
        asm("mov.b64 {%0, %1}, %2;" : "=r"(lo), "=r"(hi) : "l"(acc2[4 + 2 * i + 1]));
        o2.z = fmaxf(__uint_as_float(lo), 0.f);
        o2.w = fmaxf(__uint_as_float(hi), 0.f);
        out4[(size_t)n * 96 + q * 4 + 2 + i] = o2;
    }
}

// -----------------------------------------------------------------------
extern "C" void kernel_launch(void* const* d_in, const int* in_sizes, int n_in,
                              void* d_out, int out_size)
{
    const float* vertices    = (const float*)d_in[0];
    const int*   nh_indices  = (const int*)  d_in[1];
    const int*   int_indices = (const int*)  d_in[2];
    const float* nh_edges    = (const float*)d_in[3];
    const float* int_edges   = (const float*)d_in[4];
    // d_in[5] = is_int: unused by the reference
    const float* Wvc         = (const float*)d_in[6];
    const float* bv          = (const float*)d_in[7];
    const float* Wvn_int     = (const float*)d_in[8];
    const float* Wvn_nh      = (const float*)d_in[9];
    const float* a           = (const float*)d_in[10];
    float* out = (float*)d_out;

    cudaFuncSetAttribute(prep_kernel, cudaFuncAttributeMaxDynamicSharedMemorySize, SMEM1_TOTAL);
    dim3 wgrid(9, 4);
    wprep_kernel<<<wgrid, 256>>>(Wvc, Wvn_int, Wvn_nh);
    prep_kernel<<<(NV + 127) / 128, 256, SMEM1_TOTAL>>>(vertices, a, bv);
    gather_kernel<<<NV / 8, 192>>>(nh_indices, int_indices, nh_edges, int_edges, out);
}